// round 10
// baseline (speedup 1.0000x reference)
#include <cuda_runtime.h>
#include <cuda_fp16.h>
#include <cstdint>

#define Hh 128
#define Ww 256
#define HW (Hh*Ww)
#define NB 4
#define CIN 256
#define Tc 64
#define CCLS 19

// ---------------- scratch (allocation-free: __device__ globals) ----------------
// g_y: [nb][chunk16][pix][8 u32]; u32 = fp16 hi (upper) | fp16 lo (lower) per channel
__device__ __align__(16) uint32_t g_y[NB * 16 * HW * 8];
// g_x2: BN+ReLU output, packed fp16 hi|lo, [nb][chunk8][pix][8 u32]
__device__ __align__(16) uint32_t g_x2[NB * 8 * HW * 8];
__device__ float    g_flow[NB * 2 * HW];      // flow (fp32)
// B fragments (hi only, 2-pass): [..][lane][2] u32 = {hi_reg0, hi_reg1}
__device__ __align__(16) uint32_t g_wd[2 * 16 * 8 * 32 * 2];   // 1x1: [wh][ks16][nf8][lane][2]
__device__ __align__(16) uint32_t g_wf[9 * 8 * 8 * 32 * 2];    // 3x3: [tap][ks8][nf8][lane][2]
// flow-conv B fragments (hi+lo, 3-pass): [tap][ks4][lane][4] = {hi0,hi1,lo0,lo1}
__device__ __align__(16) uint32_t g_wfl[9 * 4 * 32 * 4];
__device__ float    g_bns[64], g_bnb[64];

// ---------------- helpers ----------------
__device__ __forceinline__ uint32_t split_pack_h(float v) {
    __half h = __float2half_rn(v);
    __half l = __float2half_rn(v - __half2float(h));
    return ((uint32_t)__half_as_ushort(h) << 16) | (uint32_t)__half_as_ushort(l);
}
__device__ __forceinline__ void split2h(float a, float b, uint32_t& hi, uint32_t& lo) {
    __half ha = __float2half_rn(a), hb = __float2half_rn(b);
    __half la = __float2half_rn(a - __half2float(ha));
    __half lb = __float2half_rn(b - __half2float(hb));
    hi = (uint32_t)__half_as_ushort(ha) | ((uint32_t)__half_as_ushort(hb) << 16);
    lo = (uint32_t)__half_as_ushort(la) | ((uint32_t)__half_as_ushort(lb) << 16);
}
__device__ __forceinline__ uint32_t hi2(uint2 v) { return (v.x >> 16) | (v.y & 0xffff0000u); }
__device__ __forceinline__ uint32_t lo2(uint2 v) { return (v.x & 0xffffu) | (v.y << 16); }

__device__ __forceinline__ void mma16816h(float (&c)[4], const uint32_t (&a)[4],
                                          uint32_t b0, uint32_t b1) {
    asm volatile(
        "mma.sync.aligned.m16n8k16.row.col.f32.f16.f16.f32 "
        "{%0,%1,%2,%3},{%4,%5,%6,%7},{%8,%9},{%0,%1,%2,%3};"
        : "+f"(c[0]), "+f"(c[1]), "+f"(c[2]), "+f"(c[3])
        : "r"(a[0]), "r"(a[1]), "r"(a[2]), "r"(a[3]), "r"(b0), "r"(b1));
}

// ============================================================================
// k_prep: weights -> fp16 fragments, BN fold
// ============================================================================
__global__ void __launch_bounds__(256) k_prep(
    const float* __restrict__ w1, const float* __restrict__ w2,
    const float* __restrict__ wf, const float* __restrict__ wfl,
    const float* __restrict__ gamma, const float* __restrict__ beta,
    const float* __restrict__ mean,  const float* __restrict__ var)
{
    int i = blockIdx.x * 256 + threadIdx.x;
    if (i < 64) {
        float s = gamma[i] * rsqrtf(var[i] + 1e-5f);
        g_bns[i] = s;
        g_bnb[i] = beta[i] - mean[i] * s;
    }
    if (i < 2 * 16 * 8 * 32 * 2) {           // 1x1 weights (16384)
        int j    = i & 1;
        int lane = (i >> 1) & 31;
        int nf   = (i >> 6) & 7;
        int ks   = (i >> 9) & 15;
        int wh   = i >> 13;
        int n   = nf * 8 + (lane >> 2);
        int ch0 = ks * 16 + (lane & 3) * 2 + j * 8;
        const float* w = wh ? w2 : w1;
        __half h0 = __float2half_rn(w[n * CIN + ch0]);
        __half h1 = __float2half_rn(w[n * CIN + ch0 + 1]);
        g_wd[(((wh * 16 + ks) * 8 + nf) * 32 + lane) * 2 + j] =
            (uint32_t)__half_as_ushort(h0) | ((uint32_t)__half_as_ushort(h1) << 16);
    }
    int m = i - 2 * 16 * 8 * 32 * 2;
    if (m >= 0 && m < 9 * 8 * 8 * 32 * 2) {  // 3x3 weights (36864)
        int j    = m & 1;
        int lane = (m >> 1) & 31;
        int nf   = (m >> 6) & 7;
        int ks   = (m >> 9) & 7;
        int tap  = m >> 12;
        int n   = nf * 8 + (lane >> 2);
        int ch0 = ks * 16 + (lane & 3) * 2 + j * 8;
        __half h0 = __float2half_rn(wf[n * (128 * 9) + ch0 * 9 + tap]);
        __half h1 = __float2half_rn(wf[n * (128 * 9) + (ch0 + 1) * 9 + tap]);
        g_wf[(((tap * 8 + ks) * 8 + nf) * 32 + lane) * 2 + j] =
            (uint32_t)__half_as_ushort(h0) | ((uint32_t)__half_as_ushort(h1) << 16);
    }
    int p = i - (2 * 16 * 8 * 32 * 2 + 9 * 8 * 8 * 32 * 2);
    if (p >= 0 && p < 9 * 4 * 32 * 2) {      // flow-conv weights (2304), hi+lo
        int j    = p & 1;
        int lane = (p >> 1) & 31;
        int ks   = (p >> 6) & 3;
        int tap  = p >> 8;
        int n   = lane >> 2;                  // only n<2 valid
        int ch0 = ks * 16 + (lane & 3) * 2 + j * 8;
        float v0 = (n < 2) ? wfl[n * 576 + ch0 * 9 + tap] : 0.f;
        float v1 = (n < 2) ? wfl[n * 576 + (ch0 + 1) * 9 + tap] : 0.f;
        uint32_t hi, lo; split2h(v0, v1, hi, lo);
        int base = ((tap * 4 + ks) * 32 + lane) * 4;
        g_wfl[base + j]     = hi;
        g_wfl[base + 2 + j] = lo;
    }
}

// profiler-steering no-op (keeps ncu sampling k2_mma)
__global__ void k_probe() {}

// ============================================================================
// k1: both 1x1 convs, fp16 2-pass mma, no smem/barriers,
// explicit next-ks A prefetch (register double buffer).
// ============================================================================
__global__ void __launch_bounds__(256, 2) k1_mma(
    const float* __restrict__ x1, const float* __restrict__ x2)
{
    const int tid = threadIdx.x, lane = tid & 31, wm = tid >> 5;
    const int pt = blockIdx.x, nb = blockIdx.y, wh = blockIdx.z;
    const int kq = lane & 3, nr = lane >> 2;

    const float* X = (wh ? x2 : x1) + (size_t)nb * CIN * HW;
    const uint2* Bw = (const uint2*)g_wd + ((size_t)wh * 16 * 8 * 32 + lane);
    const int base = pt * 256 + wm * 32 + nr;

    float acc[2][8][4];
#pragma unroll
    for (int t = 0; t < 2; t++)
#pragma unroll
        for (int f = 0; f < 8; f++)
#pragma unroll
            for (int q = 0; q < 4; q++) acc[t][f][q] = 0.f;

    float fc[2][8], fn[2][8];
    auto loadA = [&](int ks, float (&fv)[2][8]) {
        const float* Xc = X + (size_t)(ks * 16 + 2 * kq) * HW;
#pragma unroll
        for (int t = 0; t < 2; t++) {
            const int p0 = base + t * 16, p1 = p0 + 8;
            fv[t][0] = Xc[p0];          fv[t][1] = Xc[HW + p0];
            fv[t][2] = Xc[8 * HW + p0]; fv[t][3] = Xc[9 * HW + p0];
            fv[t][4] = Xc[p1];          fv[t][5] = Xc[HW + p1];
            fv[t][6] = Xc[8 * HW + p1]; fv[t][7] = Xc[9 * HW + p1];
        }
    };
    loadA(0, fc);

#pragma unroll
    for (int ks = 0; ks < 16; ks++) {
        if (ks < 15) loadA(ks + 1, fn);
        uint32_t Ahi[2][4], Alo[2][4];
#pragma unroll
        for (int t = 0; t < 2; t++) {
            split2h(fc[t][0], fc[t][1], Ahi[t][0], Alo[t][0]);
            split2h(fc[t][4], fc[t][5], Ahi[t][1], Alo[t][1]);
            split2h(fc[t][2], fc[t][3], Ahi[t][2], Alo[t][2]);
            split2h(fc[t][6], fc[t][7], Ahi[t][3], Alo[t][3]);
        }
#pragma unroll
        for (int nf = 0; nf < 8; nf++) {
            uint2 b = Bw[(ks * 8 + nf) * 32];
            mma16816h(acc[0][nf], Ahi[0], b.x, b.y);
            mma16816h(acc[0][nf], Alo[0], b.x, b.y);
            mma16816h(acc[1][nf], Ahi[1], b.x, b.y);
            mma16816h(acc[1][nf], Alo[1], b.x, b.y);
        }
#pragma unroll
        for (int t = 0; t < 2; t++)
#pragma unroll
            for (int e = 0; e < 8; e++) fc[t][e] = fn[t][e];
    }

    // epilogue: pack to g_y [chunk][pix][8]
    uint32_t* gy = g_y + (size_t)nb * 16 * HW * 8;
#pragma unroll
    for (int t = 0; t < 2; t++) {
#pragma unroll
        for (int nf = 0; nf < 8; nf++) {
            const int chunk = wh * 8 + nf;
            const int pA = base + t * 16, pB = pA + 8;
            *(uint2*)&gy[((size_t)chunk * HW + pA) * 8 + 2 * kq] =
                make_uint2(split_pack_h(acc[t][nf][0]), split_pack_h(acc[t][nf][1]));
            *(uint2*)&gy[((size_t)chunk * HW + pB) * 8 + 2 * kq] =
                make_uint2(split_pack_h(acc[t][nf][2]), split_pack_h(acc[t][nf][3]));
        }
    }
}

// ============================================================================
// k2: conv3x3 (128->64) + BN + ReLU, fp16 2-pass mma, no smem/barriers,
// explicit next-ks A prefetch. Epilogue writes packed fp16 to g_x2.
// ============================================================================
__global__ void __launch_bounds__(256, 2) k2_mma()
{
    const int tid = threadIdx.x, lane = tid & 31, wm = tid >> 5;
    const int y = blockIdx.x, nb = blockIdx.y;
    const int kq = lane & 3, nr = lane >> 2;

    float acc[2][8][4];
#pragma unroll
    for (int t = 0; t < 2; t++)
#pragma unroll
        for (int f = 0; f < 8; f++)
#pragma unroll
            for (int q = 0; q < 4; q++) acc[t][f][q] = 0.f;

    const uint2* Au = (const uint2*)(g_y + (size_t)nb * 16 * HW * 8);
    const uint2* BwL = (const uint2*)g_wf + lane;

#pragma unroll
    for (int tap = 0; tap < 9; tap++) {
        const int dy = tap / 3 - 1, dx = tap % 3 - 1;
        const int gyr = y + dy;
        const bool okY = (unsigned)gyr < (unsigned)Hh;
        int gp[4]; bool vg[4];
#pragma unroll
        for (int g = 0; g < 4; g++) {
            int gx = wm * 32 + g * 8 + nr + dx;
            vg[g] = okY && (unsigned)gx < (unsigned)Ww;
            gp[g] = gyr * Ww + gx;
        }
        const uint2* Bt = BwL + (size_t)tap * 8 * 8 * 32;

        uint2 qc[4][2], qn[4][2];
        auto loadA = [&](int ks, uint2 (&qv)[4][2]) {
            const size_t cA = (size_t)(2 * ks) * HW, cB = cA + HW;
#pragma unroll
            for (int g = 0; g < 4; g++) {
                qv[g][0] = vg[g] ? Au[(cA + gp[g]) * 4 + kq] : make_uint2(0u, 0u);
                qv[g][1] = vg[g] ? Au[(cB + gp[g]) * 4 + kq] : make_uint2(0u, 0u);
            }
        };
        loadA(0, qc);

#pragma unroll
        for (int ks = 0; ks < 8; ks++) {
            if (ks < 7) loadA(ks + 1, qn);
            uint32_t Ahi[2][4], Alo[2][4];
#pragma unroll
            for (int t = 0; t < 2; t++) {
                Ahi[t][0] = hi2(qc[2 * t][0]);     Alo[t][0] = lo2(qc[2 * t][0]);
                Ahi[t][1] = hi2(qc[2 * t + 1][0]); Alo[t][1] = lo2(qc[2 * t + 1][0]);
                Ahi[t][2] = hi2(qc[2 * t][1]);     Alo[t][2] = lo2(qc[2 * t][1]);
                Ahi[t][3] = hi2(qc[2 * t + 1][1]); Alo[t][3] = lo2(qc[2 * t + 1][1]);
            }
#pragma unroll
            for (int nf = 0; nf < 8; nf++) {
                uint2 b = Bt[(ks * 8 + nf) * 32];
                mma16816h(acc[0][nf], Ahi[0], b.x, b.y);
                mma16816h(acc[0][nf], Alo[0], b.x, b.y);
                mma16816h(acc[1][nf], Ahi[1], b.x, b.y);
                mma16816h(acc[1][nf], Alo[1], b.x, b.y);
            }
#pragma unroll
            for (int g = 0; g < 4; g++) {
                qc[g][0] = qn[g][0]; qc[g][1] = qn[g][1];
            }
        }
    }

    // epilogue: BN + ReLU -> g_x2 packed fp16 hi|lo, [chunk8][pix][8]
    uint32_t* Xo = g_x2 + (size_t)nb * 8 * HW * 8;
#pragma unroll
    for (int t = 0; t < 2; t++) {
        const int op0 = y * Ww + wm * 32 + t * 16 + nr;
        const int op1 = op0 + 8;
#pragma unroll
        for (int nf = 0; nf < 8; nf++) {
            int ch = nf * 8 + 2 * kq;
            float s0 = g_bns[ch], b0 = g_bnb[ch];
            float s1 = g_bns[ch + 1], b1 = g_bnb[ch + 1];
            float r00 = acc[t][nf][0] * s0 + b0; r00 = r00 > 0.f ? r00 : 0.f;
            float r01 = acc[t][nf][1] * s1 + b1; r01 = r01 > 0.f ? r01 : 0.f;
            float r10 = acc[t][nf][2] * s0 + b0; r10 = r10 > 0.f ? r10 : 0.f;
            float r11 = acc[t][nf][3] * s1 + b1; r11 = r11 > 0.f ? r11 : 0.f;
            *(uint2*)&Xo[((size_t)nf * HW + op0) * 8 + 2 * kq] =
                make_uint2(split_pack_h(r00), split_pack_h(r01));
            *(uint2*)&Xo[((size_t)nf * HW + op1) * 8 + 2 * kq] =
                make_uint2(split_pack_h(r10), split_pack_h(r11));
        }
    }
}

// ============================================================================
// k3: conv3x3 (64 -> 2, pad 1) -> flow, via mma (3-pass: hi*hi + lo*hi + hi*lo).
// Same tap-shift structure as k2; K=64 -> 4 k-steps; N=8 (n<2 valid).
// ============================================================================
__global__ void __launch_bounds__(256) k3_mma()
{
    const int tid = threadIdx.x, lane = tid & 31, wm = tid >> 5;
    const int y = blockIdx.x, nb = blockIdx.y;
    const int kq = lane & 3, nr = lane >> 2;

    float acc[2][4];
#pragma unroll
    for (int t = 0; t < 2; t++)
#pragma unroll
        for (int q = 0; q < 4; q++) acc[t][q] = 0.f;

    const uint2* Au = (const uint2*)(g_x2 + (size_t)nb * 8 * HW * 8);
    const uint4* BwL = (const uint4*)g_wfl + lane;

#pragma unroll
    for (int tap = 0; tap < 9; tap++) {
        const int dy = tap / 3 - 1, dx = tap % 3 - 1;
        const int gyr = y + dy;
        const bool okY = (unsigned)gyr < (unsigned)Hh;
        int gp[4]; bool vg[4];
#pragma unroll
        for (int g = 0; g < 4; g++) {
            int gx = wm * 32 + g * 8 + nr + dx;
            vg[g] = okY && (unsigned)gx < (unsigned)Ww;
            gp[g] = gyr * Ww + gx;
        }

#pragma unroll
        for (int ks = 0; ks < 4; ks++) {
            const size_t cA = (size_t)(2 * ks) * HW, cB = cA + HW;
            uint2 q[4][2];
#pragma unroll
            for (int g = 0; g < 4; g++) {
                q[g][0] = vg[g] ? Au[(cA + gp[g]) * 4 + kq] : make_uint2(0u, 0u);
                q[g][1] = vg[g] ? Au[(cB + gp[g]) * 4 + kq] : make_uint2(0u, 0u);
            }
            uint4 b = BwL[(tap * 4 + ks) * 32];
#pragma unroll
            for (int t = 0; t < 2; t++) {
                uint32_t Ahi[4] = {hi2(q[2 * t][0]), hi2(q[2 * t + 1][0]),
                                   hi2(q[2 * t][1]), hi2(q[2 * t + 1][1])};
                uint32_t Alo[4] = {lo2(q[2 * t][0]), lo2(q[2 * t + 1][0]),
                                   lo2(q[2 * t][1]), lo2(q[2 * t + 1][1])};
                mma16816h(acc[t], Ahi, b.x, b.y);
                mma16816h(acc[t], Alo, b.x, b.y);
                mma16816h(acc[t], Ahi, b.z, b.w);
            }
        }
    }

    // epilogue: lanes with kq==0 hold cols 0 (flow x) and 1 (flow y)
    if (kq == 0) {
        float* fx = g_flow + (size_t)(nb * 2) * HW;
        float* fy = fx + HW;
#pragma unroll
        for (int t = 0; t < 2; t++) {
            const int p0 = y * Ww + wm * 32 + t * 16 + nr;
            fx[p0]     = acc[t][0];
            fy[p0]     = acc[t][1];
            fx[p0 + 8] = acc[t][2];
            fy[p0 + 8] = acc[t][3];
        }
    }
}

// ============================================================================
// k4: flow_warp (torch repeat(c,1,1,1) batch-aliasing)
// ============================================================================
__global__ void __launch_bounds__(256) k_warp(
    const float* __restrict__ pred, float* __restrict__ out)
{
    const int idx = blockIdx.x * 256 + threadIdx.x;
    const int x = idx & (Ww - 1);
    const int y = (idx >> 8) & (Hh - 1);
    const int t = idx >> 15;
    const int fb = t & 3;

    const float fx = g_flow[(size_t)(fb * 2 + 0) * HW + y * Ww + x];
    const float fy = g_flow[(size_t)(fb * 2 + 1) * HW + y * Ww + x];

    const float gx = -1.f + 2.f * (float)x / (float)(Ww - 1);
    const float gy = -1.f + 2.f * (float)y / (float)(Hh - 1);
    const float sx = gx + fx / (float)Ww;
    const float sy = gy + fy / (float)Hh;
    const float ix = ((sx + 1.f) * (float)Ww - 1.f) * 0.5f;
    const float iy = ((sy + 1.f) * (float)Hh - 1.f) * 0.5f;

    const float x0f = floorf(ix), y0f = floorf(iy);
    const float wx = ix - x0f, wy = iy - y0f;
    const int x0 = (int)x0f, y0 = (int)y0f;

    const float* img = pred + (size_t)t * HW;
    auto samp = [&](int yy, int xx) -> float {
        return (xx >= 0 && xx < Ww && yy >= 0 && yy < Hh) ? img[yy * Ww + xx] : 0.f;
    };
    const float v00 = samp(y0, x0);
    const float v01 = samp(y0, x0 + 1);
    const float v10 = samp(y0 + 1, x0);
    const float v11 = samp(y0 + 1, x0 + 1);

    const float top = v00 * (1.f - wx) + v01 * wx;
    const float bot = v10 * (1.f - wx) + v11 * wx;
    out[idx] = top * (1.f - wy) + bot * wy;
}

// ============================================================================
// launch
// ============================================================================
extern "C" void kernel_launch(void* const* d_in, const int* in_sizes, int n_in,
                              void* d_out, int out_size)
{
    const float* t1_feature = (const float*)d_in[0];
    const float* t2_feature = (const float*)d_in[1];
    const float* t2_pred    = (const float*)d_in[2];
    const float* w_down1    = (const float*)d_in[3];
    const float* w_down2    = (const float*)d_in[4];
    const float* w_flow1    = (const float*)d_in[5];
    const float* bn_gamma   = (const float*)d_in[6];
    const float* bn_beta    = (const float*)d_in[7];
    const float* bn_mean    = (const float*)d_in[8];
    const float* bn_var     = (const float*)d_in[9];
    const float* w_flow2    = (const float*)d_in[10];
    float* out = (float*)d_out;

    k_prep<<<217, 256>>>(w_down1, w_down2, w_flow1, w_flow2,
                         bn_gamma, bn_beta, bn_mean, bn_var);
    k1_mma<<<dim3(128, NB, 2), 256>>>(t1_feature, t2_feature);
    k_probe<<<1, 32>>>();
    k2_mma<<<dim3(Hh, NB), 256>>>();
    k3_mma<<<dim3(Hh, NB), 256>>>();
    k_warp<<<(NB * CCLS * HW) / 256, 256>>>(t2_pred, out);
}

// round 11
// speedup vs baseline: 1.6058x; 1.6058x over previous
#include <cuda_runtime.h>
#include <cuda_fp16.h>
#include <cstdint>

#define Hh 128
#define Ww 256
#define HW (Hh*Ww)
#define NB 4
#define CIN 256
#define Tc 64
#define CCLS 19

// ---------------- scratch (allocation-free: __device__ globals) ----------------
// g_y: [nb][chunk16][pix][8 u32]; u32 = fp16 hi (upper) | fp16 lo (lower) per channel
__device__ __align__(16) uint32_t g_y[NB * 16 * HW * 8];
// g_x2: BN+ReLU output, packed fp16 hi|lo, [nb][chunk8][pix][8 u32]
__device__ __align__(16) uint32_t g_x2[NB * 8 * HW * 8];
__device__ float    g_flow[NB * 2 * HW];      // flow (fp32)
// B fragments (hi only, 2-pass): [..][lane][2] u32 = {hi_reg0, hi_reg1}
__device__ __align__(16) uint32_t g_wd[2 * 16 * 8 * 32 * 2];   // 1x1: [wh][ks16][nf8][lane][2]
__device__ __align__(16) uint32_t g_wf[9 * 8 * 8 * 32 * 2];    // 3x3: [tap][ks8][nf8][lane][2]
// flow-conv B fragments (hi+lo, 3-pass): [tap][ks4][lane][4] = {hi0,hi1,lo0,lo1}
__device__ __align__(16) uint32_t g_wfl[9 * 4 * 32 * 4];
__device__ float    g_bns[64], g_bnb[64];

// ---------------- helpers ----------------
__device__ __forceinline__ uint32_t split_pack_h(float v) {
    __half h = __float2half_rn(v);
    __half l = __float2half_rn(v - __half2float(h));
    return ((uint32_t)__half_as_ushort(h) << 16) | (uint32_t)__half_as_ushort(l);
}
__device__ __forceinline__ void split2h(float a, float b, uint32_t& hi, uint32_t& lo) {
    __half ha = __float2half_rn(a), hb = __float2half_rn(b);
    __half la = __float2half_rn(a - __half2float(ha));
    __half lb = __float2half_rn(b - __half2float(hb));
    hi = (uint32_t)__half_as_ushort(ha) | ((uint32_t)__half_as_ushort(hb) << 16);
    lo = (uint32_t)__half_as_ushort(la) | ((uint32_t)__half_as_ushort(lb) << 16);
}
__device__ __forceinline__ uint32_t hi2(uint2 v) { return (v.x >> 16) | (v.y & 0xffff0000u); }
__device__ __forceinline__ uint32_t lo2(uint2 v) { return (v.x & 0xffffu) | (v.y << 16); }

__device__ __forceinline__ void mma16816h(float (&c)[4], const uint32_t (&a)[4],
                                          uint32_t b0, uint32_t b1) {
    asm volatile(
        "mma.sync.aligned.m16n8k16.row.col.f32.f16.f16.f32 "
        "{%0,%1,%2,%3},{%4,%5,%6,%7},{%8,%9},{%0,%1,%2,%3};"
        : "+f"(c[0]), "+f"(c[1]), "+f"(c[2]), "+f"(c[3])
        : "r"(a[0]), "r"(a[1]), "r"(a[2]), "r"(a[3]), "r"(b0), "r"(b1));
}

// ============================================================================
// k_prep: weights -> fp16 fragments, BN fold
// ============================================================================
__global__ void __launch_bounds__(256) k_prep(
    const float* __restrict__ w1, const float* __restrict__ w2,
    const float* __restrict__ wf, const float* __restrict__ wfl,
    const float* __restrict__ gamma, const float* __restrict__ beta,
    const float* __restrict__ mean,  const float* __restrict__ var)
{
    int i = blockIdx.x * 256 + threadIdx.x;
    if (i < 64) {
        float s = gamma[i] * rsqrtf(var[i] + 1e-5f);
        g_bns[i] = s;
        g_bnb[i] = beta[i] - mean[i] * s;
    }
    if (i < 2 * 16 * 8 * 32 * 2) {           // 1x1 weights (16384)
        int j    = i & 1;
        int lane = (i >> 1) & 31;
        int nf   = (i >> 6) & 7;
        int ks   = (i >> 9) & 15;
        int wh   = i >> 13;
        int n   = nf * 8 + (lane >> 2);
        int ch0 = ks * 16 + (lane & 3) * 2 + j * 8;
        const float* w = wh ? w2 : w1;
        __half h0 = __float2half_rn(w[n * CIN + ch0]);
        __half h1 = __float2half_rn(w[n * CIN + ch0 + 1]);
        g_wd[(((wh * 16 + ks) * 8 + nf) * 32 + lane) * 2 + j] =
            (uint32_t)__half_as_ushort(h0) | ((uint32_t)__half_as_ushort(h1) << 16);
    }
    int m = i - 2 * 16 * 8 * 32 * 2;
    if (m >= 0 && m < 9 * 8 * 8 * 32 * 2) {  // 3x3 weights (36864)
        int j    = m & 1;
        int lane = (m >> 1) & 31;
        int nf   = (m >> 6) & 7;
        int ks   = (m >> 9) & 7;
        int tap  = m >> 12;
        int n   = nf * 8 + (lane >> 2);
        int ch0 = ks * 16 + (lane & 3) * 2 + j * 8;
        __half h0 = __float2half_rn(wf[n * (128 * 9) + ch0 * 9 + tap]);
        __half h1 = __float2half_rn(wf[n * (128 * 9) + (ch0 + 1) * 9 + tap]);
        g_wf[(((tap * 8 + ks) * 8 + nf) * 32 + lane) * 2 + j] =
            (uint32_t)__half_as_ushort(h0) | ((uint32_t)__half_as_ushort(h1) << 16);
    }
    int p = i - (2 * 16 * 8 * 32 * 2 + 9 * 8 * 8 * 32 * 2);
    if (p >= 0 && p < 9 * 4 * 32 * 2) {      // flow-conv weights (2304), hi+lo
        int j    = p & 1;
        int lane = (p >> 1) & 31;
        int ks   = (p >> 6) & 3;
        int tap  = p >> 8;
        int n   = lane >> 2;                  // only n<2 valid
        int ch0 = ks * 16 + (lane & 3) * 2 + j * 8;
        float v0 = (n < 2) ? wfl[n * 576 + ch0 * 9 + tap] : 0.f;
        float v1 = (n < 2) ? wfl[n * 576 + (ch0 + 1) * 9 + tap] : 0.f;
        uint32_t hi, lo; split2h(v0, v1, hi, lo);
        int base = ((tap * 4 + ks) * 32 + lane) * 4;
        g_wfl[base + j]     = hi;
        g_wfl[base + 2 + j] = lo;
    }
}

// profiler-steering no-op (keeps ncu sampling k2_mma)
__global__ void k_probe() {}

// ============================================================================
// k1: both 1x1 convs, fp16 2-pass mma, no smem/barriers, no explicit prefetch
// (round-8 structure: fits 128 regs without spills).
// ============================================================================
__global__ void __launch_bounds__(256, 2) k1_mma(
    const float* __restrict__ x1, const float* __restrict__ x2)
{
    const int tid = threadIdx.x, lane = tid & 31, wm = tid >> 5;
    const int pt = blockIdx.x, nb = blockIdx.y, wh = blockIdx.z;
    const int kq = lane & 3, nr = lane >> 2;

    const float* X = (wh ? x2 : x1) + (size_t)nb * CIN * HW;
    const uint2* Bw = (const uint2*)g_wd + ((size_t)wh * 16 * 8 * 32 + lane);
    const int base = pt * 256 + wm * 32 + nr;

    float acc[2][8][4];
#pragma unroll
    for (int t = 0; t < 2; t++)
#pragma unroll
        for (int f = 0; f < 8; f++)
#pragma unroll
            for (int q = 0; q < 4; q++) acc[t][f][q] = 0.f;

#pragma unroll 4
    for (int ks = 0; ks < 16; ks++) {
        const float* Xc = X + (size_t)(ks * 16 + 2 * kq) * HW;
        uint32_t Ahi[2][4], Alo[2][4];
#pragma unroll
        for (int t = 0; t < 2; t++) {
            const int p0 = base + t * 16, p1 = p0 + 8;
            float f0 = Xc[p0],          f1 = Xc[HW + p0];
            float f2 = Xc[8 * HW + p0], f3 = Xc[9 * HW + p0];
            float f4 = Xc[p1],          f5 = Xc[HW + p1];
            float f6 = Xc[8 * HW + p1], f7 = Xc[9 * HW + p1];
            split2h(f0, f1, Ahi[t][0], Alo[t][0]);
            split2h(f4, f5, Ahi[t][1], Alo[t][1]);
            split2h(f2, f3, Ahi[t][2], Alo[t][2]);
            split2h(f6, f7, Ahi[t][3], Alo[t][3]);
        }
#pragma unroll
        for (int nf = 0; nf < 8; nf++) {
            uint2 b = Bw[(ks * 8 + nf) * 32];
            mma16816h(acc[0][nf], Ahi[0], b.x, b.y);
            mma16816h(acc[0][nf], Alo[0], b.x, b.y);
            mma16816h(acc[1][nf], Ahi[1], b.x, b.y);
            mma16816h(acc[1][nf], Alo[1], b.x, b.y);
        }
    }

    // epilogue: pack to g_y [chunk][pix][8]
    uint32_t* gy = g_y + (size_t)nb * 16 * HW * 8;
#pragma unroll
    for (int t = 0; t < 2; t++) {
#pragma unroll
        for (int nf = 0; nf < 8; nf++) {
            const int chunk = wh * 8 + nf;
            const int pA = base + t * 16, pB = pA + 8;
            *(uint2*)&gy[((size_t)chunk * HW + pA) * 8 + 2 * kq] =
                make_uint2(split_pack_h(acc[t][nf][0]), split_pack_h(acc[t][nf][1]));
            *(uint2*)&gy[((size_t)chunk * HW + pB) * 8 + 2 * kq] =
                make_uint2(split_pack_h(acc[t][nf][2]), split_pack_h(acc[t][nf][3]));
        }
    }
}

// ============================================================================
// k2: conv3x3 (128->64) + BN + ReLU, fp16 2-pass mma, no smem/barriers,
// no explicit prefetch (round-8 mainloop). Epilogue writes packed fp16 g_x2.
// ============================================================================
__global__ void __launch_bounds__(256, 2) k2_mma()
{
    const int tid = threadIdx.x, lane = tid & 31, wm = tid >> 5;
    const int y = blockIdx.x, nb = blockIdx.y;
    const int kq = lane & 3, nr = lane >> 2;

    float acc[2][8][4];
#pragma unroll
    for (int t = 0; t < 2; t++)
#pragma unroll
        for (int f = 0; f < 8; f++)
#pragma unroll
            for (int q = 0; q < 4; q++) acc[t][f][q] = 0.f;

    const uint2* Au = (const uint2*)(g_y + (size_t)nb * 16 * HW * 8);
    const uint2* BwL = (const uint2*)g_wf + lane;

#pragma unroll
    for (int tap = 0; tap < 9; tap++) {
        const int dy = tap / 3 - 1, dx = tap % 3 - 1;
        const int gyr = y + dy;
        const bool okY = (unsigned)gyr < (unsigned)Hh;
        int gp[4]; bool vg[4];
#pragma unroll
        for (int g = 0; g < 4; g++) {
            int gx = wm * 32 + g * 8 + nr + dx;
            vg[g] = okY && (unsigned)gx < (unsigned)Ww;
            gp[g] = gyr * Ww + gx;
        }
        const uint2* Bt = BwL + (size_t)tap * 8 * 8 * 32;

#pragma unroll
        for (int ks = 0; ks < 8; ks++) {
            const size_t cA = (size_t)(2 * ks) * HW, cB = cA + HW;
            uint2 q[4][2];
#pragma unroll
            for (int g = 0; g < 4; g++) {
                q[g][0] = vg[g] ? Au[(cA + gp[g]) * 4 + kq] : make_uint2(0u, 0u);
                q[g][1] = vg[g] ? Au[(cB + gp[g]) * 4 + kq] : make_uint2(0u, 0u);
            }
            uint32_t Ahi[2][4], Alo[2][4];
#pragma unroll
            for (int t = 0; t < 2; t++) {
                Ahi[t][0] = hi2(q[2 * t][0]);     Alo[t][0] = lo2(q[2 * t][0]);
                Ahi[t][1] = hi2(q[2 * t + 1][0]); Alo[t][1] = lo2(q[2 * t + 1][0]);
                Ahi[t][2] = hi2(q[2 * t][1]);     Alo[t][2] = lo2(q[2 * t][1]);
                Ahi[t][3] = hi2(q[2 * t + 1][1]); Alo[t][3] = lo2(q[2 * t + 1][1]);
            }
#pragma unroll
            for (int nf = 0; nf < 8; nf++) {
                uint2 b = Bt[(ks * 8 + nf) * 32];
                mma16816h(acc[0][nf], Ahi[0], b.x, b.y);
                mma16816h(acc[0][nf], Alo[0], b.x, b.y);
                mma16816h(acc[1][nf], Ahi[1], b.x, b.y);
                mma16816h(acc[1][nf], Alo[1], b.x, b.y);
            }
        }
    }

    // epilogue: BN + ReLU -> g_x2 packed fp16 hi|lo, [chunk8][pix][8]
    uint32_t* Xo = g_x2 + (size_t)nb * 8 * HW * 8;
#pragma unroll
    for (int t = 0; t < 2; t++) {
        const int op0 = y * Ww + wm * 32 + t * 16 + nr;
        const int op1 = op0 + 8;
#pragma unroll
        for (int nf = 0; nf < 8; nf++) {
            int ch = nf * 8 + 2 * kq;
            float s0 = g_bns[ch], b0 = g_bnb[ch];
            float s1 = g_bns[ch + 1], b1 = g_bnb[ch + 1];
            float r00 = acc[t][nf][0] * s0 + b0; r00 = r00 > 0.f ? r00 : 0.f;
            float r01 = acc[t][nf][1] * s1 + b1; r01 = r01 > 0.f ? r01 : 0.f;
            float r10 = acc[t][nf][2] * s0 + b0; r10 = r10 > 0.f ? r10 : 0.f;
            float r11 = acc[t][nf][3] * s1 + b1; r11 = r11 > 0.f ? r11 : 0.f;
            *(uint2*)&Xo[((size_t)nf * HW + op0) * 8 + 2 * kq] =
                make_uint2(split_pack_h(r00), split_pack_h(r01));
            *(uint2*)&Xo[((size_t)nf * HW + op1) * 8 + 2 * kq] =
                make_uint2(split_pack_h(r10), split_pack_h(r11));
        }
    }
}

// ============================================================================
// k3: conv3x3 (64 -> 2, pad 1) -> flow, via mma (3-pass: hi*hi + lo*hi + hi*lo).
// Same tap-shift structure as k2; K=64 -> 4 k-steps; N=8 (n<2 valid).
// ============================================================================
__global__ void __launch_bounds__(256) k3_mma()
{
    const int tid = threadIdx.x, lane = tid & 31, wm = tid >> 5;
    const int y = blockIdx.x, nb = blockIdx.y;
    const int kq = lane & 3, nr = lane >> 2;

    float acc[2][4];
#pragma unroll
    for (int t = 0; t < 2; t++)
#pragma unroll
        for (int q = 0; q < 4; q++) acc[t][q] = 0.f;

    const uint2* Au = (const uint2*)(g_x2 + (size_t)nb * 8 * HW * 8);
    const uint4* BwL = (const uint4*)g_wfl + lane;

#pragma unroll
    for (int tap = 0; tap < 9; tap++) {
        const int dy = tap / 3 - 1, dx = tap % 3 - 1;
        const int gyr = y + dy;
        const bool okY = (unsigned)gyr < (unsigned)Hh;
        int gp[4]; bool vg[4];
#pragma unroll
        for (int g = 0; g < 4; g++) {
            int gx = wm * 32 + g * 8 + nr + dx;
            vg[g] = okY && (unsigned)gx < (unsigned)Ww;
            gp[g] = gyr * Ww + gx;
        }

#pragma unroll
        for (int ks = 0; ks < 4; ks++) {
            const size_t cA = (size_t)(2 * ks) * HW, cB = cA + HW;
            uint2 q[4][2];
#pragma unroll
            for (int g = 0; g < 4; g++) {
                q[g][0] = vg[g] ? Au[(cA + gp[g]) * 4 + kq] : make_uint2(0u, 0u);
                q[g][1] = vg[g] ? Au[(cB + gp[g]) * 4 + kq] : make_uint2(0u, 0u);
            }
            uint4 b = BwL[(tap * 4 + ks) * 32];
#pragma unroll
            for (int t = 0; t < 2; t++) {
                uint32_t Ahi[4] = {hi2(q[2 * t][0]), hi2(q[2 * t + 1][0]),
                                   hi2(q[2 * t][1]), hi2(q[2 * t + 1][1])};
                uint32_t Alo[4] = {lo2(q[2 * t][0]), lo2(q[2 * t + 1][0]),
                                   lo2(q[2 * t][1]), lo2(q[2 * t + 1][1])};
                mma16816h(acc[t], Ahi, b.x, b.y);
                mma16816h(acc[t], Alo, b.x, b.y);
                mma16816h(acc[t], Ahi, b.z, b.w);
            }
        }
    }

    // epilogue: lanes with kq==0 hold cols 0 (flow x) and 1 (flow y)
    if (kq == 0) {
        float* fx = g_flow + (size_t)(nb * 2) * HW;
        float* fy = fx + HW;
#pragma unroll
        for (int t = 0; t < 2; t++) {
            const int p0 = y * Ww + wm * 32 + t * 16 + nr;
            fx[p0]     = acc[t][0];
            fy[p0]     = acc[t][1];
            fx[p0 + 8] = acc[t][2];
            fy[p0 + 8] = acc[t][3];
        }
    }
}

// ============================================================================
// k4: flow_warp (torch repeat(c,1,1,1) batch-aliasing)
// ============================================================================
__global__ void __launch_bounds__(256) k_warp(
    const float* __restrict__ pred, float* __restrict__ out)
{
    const int idx = blockIdx.x * 256 + threadIdx.x;
    const int x = idx & (Ww - 1);
    const int y = (idx >> 8) & (Hh - 1);
    const int t = idx >> 15;
    const int fb = t & 3;

    const float fx = g_flow[(size_t)(fb * 2 + 0) * HW + y * Ww + x];
    const float fy = g_flow[(size_t)(fb * 2 + 1) * HW + y * Ww + x];

    const float gx = -1.f + 2.f * (float)x / (float)(Ww - 1);
    const float gy = -1.f + 2.f * (float)y / (float)(Hh - 1);
    const float sx = gx + fx / (float)Ww;
    const float sy = gy + fy / (float)Hh;
    const float ix = ((sx + 1.f) * (float)Ww - 1.f) * 0.5f;
    const float iy = ((sy + 1.f) * (float)Hh - 1.f) * 0.5f;

    const float x0f = floorf(ix), y0f = floorf(iy);
    const float wx = ix - x0f, wy = iy - y0f;
    const int x0 = (int)x0f, y0 = (int)y0f;

    const float* img = pred + (size_t)t * HW;
    auto samp = [&](int yy, int xx) -> float {
        return (xx >= 0 && xx < Ww && yy >= 0 && yy < Hh) ? img[yy * Ww + xx] : 0.f;
    };
    const float v00 = samp(y0, x0);
    const float v01 = samp(y0, x0 + 1);
    const float v10 = samp(y0 + 1, x0);
    const float v11 = samp(y0 + 1, x0 + 1);

    const float top = v00 * (1.f - wx) + v01 * wx;
    const float bot = v10 * (1.f - wx) + v11 * wx;
    out[idx] = top * (1.f - wy) + bot * wy;
}

// ============================================================================
// launch
// ============================================================================
extern "C" void kernel_launch(void* const* d_in, const int* in_sizes, int n_in,
                              void* d_out, int out_size)
{
    const float* t1_feature = (const float*)d_in[0];
    const float* t2_feature = (const float*)d_in[1];
    const float* t2_pred    = (const float*)d_in[2];
    const float* w_down1    = (const float*)d_in[3];
    const float* w_down2    = (const float*)d_in[4];
    const float* w_flow1    = (const float*)d_in[5];
    const float* bn_gamma   = (const float*)d_in[6];
    const float* bn_beta    = (const float*)d_in[7];
    const float* bn_mean    = (const float*)d_in[8];
    const float* bn_var     = (const float*)d_in[9];
    const float* w_flow2    = (const float*)d_in[10];
    float* out = (float*)d_out;

    k_prep<<<217, 256>>>(w_down1, w_down2, w_flow1, w_flow2,
                         bn_gamma, bn_beta, bn_mean, bn_var);
    k1_mma<<<dim3(128, NB, 2), 256>>>(t1_feature, t2_feature);
    k_probe<<<1, 32>>>();
    k2_mma<<<dim3(Hh, NB), 256>>>();
    k3_mma<<<dim3(Hh, NB), 256>>>();
    k_warp<<<(NB * CCLS * HW) / 256, 256>>>(t2_pred, out);
}

// round 13
// speedup vs baseline: 1.6193x; 1.0084x over previous
#include <cuda_runtime.h>
#include <cuda_fp16.h>
#include <cstdint>

#define Hh 128
#define Ww 256
#define HW (Hh*Ww)
#define NB 4
#define CIN 256
#define Tc 64
#define CCLS 19

// ---------------- scratch (allocation-free: __device__ globals) ----------------
// g_y: [nb][chunk16][pix][8 u32]; u32 = fp16 hi (upper) | fp16 lo (lower) per channel
__device__ __align__(16) uint32_t g_y[NB * 16 * HW * 8];
// g_x2: BN+ReLU output, packed fp16 hi|lo, [nb][chunk8][pix][8 u32]
__device__ __align__(16) uint32_t g_x2[NB * 8 * HW * 8];
__device__ float    g_flow[NB * 2 * HW];      // flow (fp32)
// B fragments (hi only, 2-pass): [..][lane][2] u32 = {hi_reg0, hi_reg1}
__device__ __align__(16) uint32_t g_wd[2 * 16 * 8 * 32 * 2];   // 1x1: [wh][ks16][nf8][lane][2]
__device__ __align__(16) uint32_t g_wf[9 * 8 * 8 * 32 * 2];    // 3x3: [tap][ks8][nf8][lane][2]
// flow-conv B fragments (hi+lo, 3-pass): [tap][ks4][lane][4] = {hi0,hi1,lo0,lo1}
__device__ __align__(16) uint32_t g_wfl[9 * 4 * 32 * 4];
__device__ float    g_bns[64], g_bnb[64];

// k2 staging geometry: [row3][chunk2][px 260][8 u32]; px slot = pixel+1 (0 & 257 zero)
#define ABUF (3 * 2 * 260 * 8)          // u32 per buffer = 12480 (49,920 B)
#define K2_SMEM (2 * ABUF * 4)          // 99,840 B
// k1 staging: [ch16][px 260] fp32 (stride padded for banks)
#define XBUF (16 * 260)                 // floats per buffer (16,640 B)
#define K1_SMEM (2 * XBUF * 4)          // 33,280 B

// ---------------- helpers ----------------
__device__ __forceinline__ uint32_t smem_u32(const void* p) {
    uint32_t a;
    asm("{ .reg .u64 t; cvta.to.shared.u64 t, %1; cvt.u32.u64 %0, t; }" : "=r"(a) : "l"(p));
    return a;
}
__device__ __forceinline__ void cp_async16(uint32_t saddr, const void* g) {
    asm volatile("cp.async.cg.shared.global [%0], [%1], 16;" :: "r"(saddr), "l"(g));
}
__device__ __forceinline__ void cp_async16z(uint32_t saddr, const void* g, int srcsize) {
    asm volatile("cp.async.cg.shared.global [%0], [%1], 16, %2;"
                 :: "r"(saddr), "l"(g), "r"(srcsize));
}
__device__ __forceinline__ void cp_commit() { asm volatile("cp.async.commit_group;"); }
__device__ __forceinline__ void cp_wait0()  { asm volatile("cp.async.wait_group 0;"); }

__device__ __forceinline__ uint32_t split_pack_h(float v) {
    __half h = __float2half_rn(v);
    __half l = __float2half_rn(v - __half2float(h));
    return ((uint32_t)__half_as_ushort(h) << 16) | (uint32_t)__half_as_ushort(l);
}
__device__ __forceinline__ void split2h(float a, float b, uint32_t& hi, uint32_t& lo) {
    __half ha = __float2half_rn(a), hb = __float2half_rn(b);
    __half la = __float2half_rn(a - __half2float(ha));
    __half lb = __float2half_rn(b - __half2float(hb));
    hi = (uint32_t)__half_as_ushort(ha) | ((uint32_t)__half_as_ushort(hb) << 16);
    lo = (uint32_t)__half_as_ushort(la) | ((uint32_t)__half_as_ushort(lb) << 16);
}
__device__ __forceinline__ uint32_t hi2(uint2 v) { return (v.x >> 16) | (v.y & 0xffff0000u); }
__device__ __forceinline__ uint32_t lo2(uint2 v) { return (v.x & 0xffffu) | (v.y << 16); }

__device__ __forceinline__ void mma16816h(float (&c)[4], const uint32_t (&a)[4],
                                          uint32_t b0, uint32_t b1) {
    asm volatile(
        "mma.sync.aligned.m16n8k16.row.col.f32.f16.f16.f32 "
        "{%0,%1,%2,%3},{%4,%5,%6,%7},{%8,%9},{%0,%1,%2,%3};"
        : "+f"(c[0]), "+f"(c[1]), "+f"(c[2]), "+f"(c[3])
        : "r"(a[0]), "r"(a[1]), "r"(a[2]), "r"(a[3]), "r"(b0), "r"(b1));
}

// ============================================================================
// k_prep: weights -> fp16 fragments, BN fold
// ============================================================================
__global__ void __launch_bounds__(256) k_prep(
    const float* __restrict__ w1, const float* __restrict__ w2,
    const float* __restrict__ wf, const float* __restrict__ wfl,
    const float* __restrict__ gamma, const float* __restrict__ beta,
    const float* __restrict__ mean,  const float* __restrict__ var)
{
    int i = blockIdx.x * 256 + threadIdx.x;
    if (i < 64) {
        float s = gamma[i] * rsqrtf(var[i] + 1e-5f);
        g_bns[i] = s;
        g_bnb[i] = beta[i] - mean[i] * s;
    }
    if (i < 2 * 16 * 8 * 32 * 2) {           // 1x1 weights (16384)
        int j    = i & 1;
        int lane = (i >> 1) & 31;
        int nf   = (i >> 6) & 7;
        int ks   = (i >> 9) & 15;
        int wh   = i >> 13;
        int n   = nf * 8 + (lane >> 2);
        int ch0 = ks * 16 + (lane & 3) * 2 + j * 8;
        const float* w = wh ? w2 : w1;
        __half h0 = __float2half_rn(w[n * CIN + ch0]);
        __half h1 = __float2half_rn(w[n * CIN + ch0 + 1]);
        g_wd[(((wh * 16 + ks) * 8 + nf) * 32 + lane) * 2 + j] =
            (uint32_t)__half_as_ushort(h0) | ((uint32_t)__half_as_ushort(h1) << 16);
    }
    int m = i - 2 * 16 * 8 * 32 * 2;
    if (m >= 0 && m < 9 * 8 * 8 * 32 * 2) {  // 3x3 weights (36864)
        int j    = m & 1;
        int lane = (m >> 1) & 31;
        int nf   = (m >> 6) & 7;
        int ks   = (m >> 9) & 7;
        int tap  = m >> 12;
        int n   = nf * 8 + (lane >> 2);
        int ch0 = ks * 16 + (lane & 3) * 2 + j * 8;
        __half h0 = __float2half_rn(wf[n * (128 * 9) + ch0 * 9 + tap]);
        __half h1 = __float2half_rn(wf[n * (128 * 9) + (ch0 + 1) * 9 + tap]);
        g_wf[(((tap * 8 + ks) * 8 + nf) * 32 + lane) * 2 + j] =
            (uint32_t)__half_as_ushort(h0) | ((uint32_t)__half_as_ushort(h1) << 16);
    }
    int p = i - (2 * 16 * 8 * 32 * 2 + 9 * 8 * 8 * 32 * 2);
    if (p >= 0 && p < 9 * 4 * 32 * 2) {      // flow-conv weights (2304), hi+lo
        int j    = p & 1;
        int lane = (p >> 1) & 31;
        int ks   = (p >> 6) & 3;
        int tap  = p >> 8;
        int n   = lane >> 2;                  // only n<2 valid
        int ch0 = ks * 16 + (lane & 3) * 2 + j * 8;
        float v0 = (n < 2) ? wfl[n * 576 + ch0 * 9 + tap] : 0.f;
        float v1 = (n < 2) ? wfl[n * 576 + (ch0 + 1) * 9 + tap] : 0.f;
        uint32_t hi, lo; split2h(v0, v1, hi, lo);
        int base = ((tap * 4 + ks) * 32 + lane) * 4;
        g_wfl[base + j]     = hi;
        g_wfl[base + 2 + j] = lo;
    }
}

// profiler-steering no-op (keeps ncu sampling k2_mma)
__global__ void k_probe() {}

// ============================================================================
// k1: both 1x1 convs, fp16 2-pass mma. A staged per-ks via cp.async (double
// buffer in SMEM) -> latency hidden with zero extra registers.
// ============================================================================
__global__ void __launch_bounds__(256, 2) k1_mma(
    const float* __restrict__ x1, const float* __restrict__ x2)
{
    extern __shared__ float sX[];            // [2][16][260] floats
    const int tid = threadIdx.x, lane = tid & 31, wm = tid >> 5;
    const int pt = blockIdx.x, nb = blockIdx.y, wh = blockIdx.z;
    const int kq = lane & 3, nr = lane >> 2;
    const uint32_t sxa = smem_u32(sX);

    const float* X = (wh ? x2 : x1) + (size_t)nb * CIN * HW + pt * 256;
    const uint2* Bw = (const uint2*)g_wd + ((size_t)wh * 16 * 8 * 32 + lane);
    const int base = pt * 256 + wm * 32 + nr;

    float acc[2][8][4];
#pragma unroll
    for (int t = 0; t < 2; t++)
#pragma unroll
        for (int f = 0; f < 8; f++)
#pragma unroll
            for (int q = 0; q < 4; q++) acc[t][f][q] = 0.f;

    auto stage = [&](int ks, int b) {
#pragma unroll
        for (int it = 0; it < 4; it++) {
            int i = tid + it * 256;
            int ch = i >> 6, quad = i & 63;
            const float* src = X + (size_t)(ks * 16 + ch) * HW + quad * 4;
            uint32_t dst = sxa + (uint32_t)(b * XBUF + ch * 260 + quad * 4) * 4u;
            cp_async16(dst, src);
        }
    };

    stage(0, 0);
    cp_commit();

    for (int ks = 0; ks < 16; ks++) {
        cp_wait0();
        __syncthreads();
        if (ks < 15) { stage(ks + 1, (ks + 1) & 1); cp_commit(); }

        const float* buf = sX + (ks & 1) * XBUF;
        uint32_t Ahi[2][4], Alo[2][4];
#pragma unroll
        for (int t = 0; t < 2; t++) {
            const int p0 = wm * 32 + t * 16 + nr, p1 = p0 + 8;
            float f0 = buf[(2 * kq) * 260 + p0],     f1 = buf[(2 * kq + 1) * 260 + p0];
            float f2 = buf[(2 * kq + 8) * 260 + p0], f3 = buf[(2 * kq + 9) * 260 + p0];
            float f4 = buf[(2 * kq) * 260 + p1],     f5 = buf[(2 * kq + 1) * 260 + p1];
            float f6 = buf[(2 * kq + 8) * 260 + p1], f7 = buf[(2 * kq + 9) * 260 + p1];
            split2h(f0, f1, Ahi[t][0], Alo[t][0]);
            split2h(f4, f5, Ahi[t][1], Alo[t][1]);
            split2h(f2, f3, Ahi[t][2], Alo[t][2]);
            split2h(f6, f7, Ahi[t][3], Alo[t][3]);
        }
#pragma unroll
        for (int nf = 0; nf < 8; nf++) {
            uint2 b = Bw[(ks * 8 + nf) * 32];
            mma16816h(acc[0][nf], Ahi[0], b.x, b.y);
            mma16816h(acc[0][nf], Alo[0], b.x, b.y);
            mma16816h(acc[1][nf], Ahi[1], b.x, b.y);
            mma16816h(acc[1][nf], Alo[1], b.x, b.y);
        }
    }

    // epilogue: pack to g_y [chunk][pix][8]
    uint32_t* gy = g_y + (size_t)nb * 16 * HW * 8;
#pragma unroll
    for (int t = 0; t < 2; t++) {
#pragma unroll
        for (int nf = 0; nf < 8; nf++) {
            const int chunk = wh * 8 + nf;
            const int pA = base + t * 16, pB = pA + 8;
            *(uint2*)&gy[((size_t)chunk * HW + pA) * 8 + 2 * kq] =
                make_uint2(split_pack_h(acc[t][nf][0]), split_pack_h(acc[t][nf][1]));
            *(uint2*)&gy[((size_t)chunk * HW + pB) * 8 + 2 * kq] =
                make_uint2(split_pack_h(acc[t][nf][2]), split_pack_h(acc[t][nf][3]));
        }
    }
}

// ============================================================================
// k2: conv3x3 (128->64) + BN + ReLU, fp16 2-pass mma.
// Loop order: ks outer (8 rounds), taps inner (9). Per round, A (3 rows x 16ch
// x 256px packed) staged via cp.async double-buffer; taps read SMEM (LDS.64,
// conflict-free). y-borders via zfill, x-borders via pre-zeroed columns.
// ============================================================================
__global__ void __launch_bounds__(256, 2) k2_mma()
{
    extern __shared__ uint32_t sA[];         // [2][3][2][260][8] u32
    const int tid = threadIdx.x, lane = tid & 31, wm = tid >> 5;
    const int y = blockIdx.x, nb = blockIdx.y;
    const int kq = lane & 3, nr = lane >> 2;
    const uint32_t saa = smem_u32(sA);

    float acc[2][8][4];
#pragma unroll
    for (int t = 0; t < 2; t++)
#pragma unroll
        for (int f = 0; f < 8; f++)
#pragma unroll
            for (int q = 0; q < 4; q++) acc[t][f][q] = 0.f;

    // zero the border columns (px slots 0 and 257) of both buffers, once
    for (int i = tid; i < 2 * 6 * 2 * 8; i += 256) {   // 192 words
        int j = i & 7, col = (i >> 3) & 1, rc = (i >> 4) % 6, b = i / 96;
        sA[b * ABUF + (rc * 260 + (col ? 257 : 0)) * 8 + j] = 0u;
    }

    const uint32_t* gyb = g_y + (size_t)nb * 16 * HW * 8;
    const uint2* BwL = (const uint2*)g_wf + lane;

    auto stage = [&](int ks, int b) {
#pragma unroll
        for (int it = 0; it < 12; it++) {
            int i = tid + it * 256;
            int half = i & 1;
            int px = (i >> 1) & 255;
            int rc = i >> 9;                 // 0..5: row*2+chunk
            int row = rc >> 1, chunk = rc & 1;
            int gyr = y + row - 1;
            int ok = ((unsigned)gyr < (unsigned)Hh) ? 16 : 0;
            int gyc = (gyr < 0) ? 0 : (gyr > Hh - 1 ? Hh - 1 : gyr);
            const uint32_t* src = gyb + ((size_t)(2 * ks + chunk) * HW + gyc * Ww + px) * 8 + half * 4;
            uint32_t dst = saa + (uint32_t)(b * ABUF + (rc * 260 + 1 + px) * 8 + half * 4) * 4u;
            cp_async16z(dst, src, ok);
        }
    };

    stage(0, 0);
    cp_commit();

    for (int ks = 0; ks < 8; ks++) {
        cp_wait0();
        __syncthreads();
        if (ks < 7) { stage(ks + 1, (ks + 1) & 1); cp_commit(); }

        const uint32_t* buf = sA + (ks & 1) * ABUF;
#pragma unroll
        for (int tap = 0; tap < 9; tap++) {
            const int row = tap / 3, dx = tap % 3 - 1;
            uint2 q[4][2];
#pragma unroll
            for (int g = 0; g < 4; g++) {
                const int px = wm * 32 + g * 8 + nr + dx + 1;
                q[g][0] = *(const uint2*)&buf[((row * 2 + 0) * 260 + px) * 8 + 2 * kq];
                q[g][1] = *(const uint2*)&buf[((row * 2 + 1) * 260 + px) * 8 + 2 * kq];
            }
            uint32_t Ahi[2][4], Alo[2][4];
#pragma unroll
            for (int t = 0; t < 2; t++) {
                Ahi[t][0] = hi2(q[2 * t][0]);     Alo[t][0] = lo2(q[2 * t][0]);
                Ahi[t][1] = hi2(q[2 * t + 1][0]); Alo[t][1] = lo2(q[2 * t + 1][0]);
                Ahi[t][2] = hi2(q[2 * t][1]);     Alo[t][2] = lo2(q[2 * t][1]);
                Ahi[t][3] = hi2(q[2 * t + 1][1]); Alo[t][3] = lo2(q[2 * t + 1][1]);
            }
#pragma unroll
            for (int nf = 0; nf < 8; nf++) {
                uint2 b = BwL[((tap * 8 + ks) * 8 + nf) * 32];
                mma16816h(acc[0][nf], Ahi[0], b.x, b.y);
                mma16816h(acc[0][nf], Alo[0], b.x, b.y);
                mma16816h(acc[1][nf], Ahi[1], b.x, b.y);
                mma16816h(acc[1][nf], Alo[1], b.x, b.y);
            }
        }
    }

    // epilogue: BN + ReLU -> g_x2 packed fp16 hi|lo, [chunk8][pix][8]
    uint32_t* Xo = g_x2 + (size_t)nb * 8 * HW * 8;
#pragma unroll
    for (int t = 0; t < 2; t++) {
        const int op0 = y * Ww + wm * 32 + t * 16 + nr;
        const int op1 = op0 + 8;
#pragma unroll
        for (int nf = 0; nf < 8; nf++) {
            int ch = nf * 8 + 2 * kq;
            float s0 = g_bns[ch], b0 = g_bnb[ch];
            float s1 = g_bns[ch + 1], b1 = g_bnb[ch + 1];
            float r00 = acc[t][nf][0] * s0 + b0; r00 = r00 > 0.f ? r00 : 0.f;
            float r01 = acc[t][nf][1] * s1 + b1; r01 = r01 > 0.f ? r01 : 0.f;
            float r10 = acc[t][nf][2] * s0 + b0; r10 = r10 > 0.f ? r10 : 0.f;
            float r11 = acc[t][nf][3] * s1 + b1; r11 = r11 > 0.f ? r11 : 0.f;
            *(uint2*)&Xo[((size_t)nf * HW + op0) * 8 + 2 * kq] =
                make_uint2(split_pack_h(r00), split_pack_h(r01));
            *(uint2*)&Xo[((size_t)nf * HW + op1) * 8 + 2 * kq] =
                make_uint2(split_pack_h(r10), split_pack_h(r11));
        }
    }
}

// ============================================================================
// k3: conv3x3 (64 -> 2, pad 1) -> flow, via mma (3-pass: hi*hi + lo*hi + hi*lo).
// ============================================================================
__global__ void __launch_bounds__(256) k3_mma()
{
    const int tid = threadIdx.x, lane = tid & 31, wm = tid >> 5;
    const int y = blockIdx.x, nb = blockIdx.y;
    const int kq = lane & 3, nr = lane >> 2;

    float acc[2][4];
#pragma unroll
    for (int t = 0; t < 2; t++)
#pragma unroll
        for (int q = 0; q < 4; q++) acc[t][q] = 0.f;

    const uint2* Au = (const uint2*)(g_x2 + (size_t)nb * 8 * HW * 8);
    const uint4* BwL = (const uint4*)g_wfl + lane;

#pragma unroll
    for (int tap = 0; tap < 9; tap++) {
        const int dy = tap / 3 - 1, dx = tap % 3 - 1;
        const int gyr = y + dy;
        const bool okY = (unsigned)gyr < (unsigned)Hh;
        int gp[4]; bool vg[4];
#pragma unroll
        for (int g = 0; g < 4; g++) {
            int gx = wm * 32 + g * 8 + nr + dx;
            vg[g] = okY && (unsigned)gx < (unsigned)Ww;
            gp[g] = gyr * Ww + gx;
        }

#pragma unroll
        for (int ks = 0; ks < 4; ks++) {
            const size_t cA = (size_t)(2 * ks) * HW, cB = cA + HW;
            uint2 q[4][2];
#pragma unroll
            for (int g = 0; g < 4; g++) {
                q[g][0] = vg[g] ? Au[(cA + gp[g]) * 4 + kq] : make_uint2(0u, 0u);
                q[g][1] = vg[g] ? Au[(cB + gp[g]) * 4 + kq] : make_uint2(0u, 0u);
            }
            uint4 b = BwL[(tap * 4 + ks) * 32];
#pragma unroll
            for (int t = 0; t < 2; t++) {
                uint32_t Ahi[4] = {hi2(q[2 * t][0]), hi2(q[2 * t + 1][0]),
                                   hi2(q[2 * t][1]), hi2(q[2 * t + 1][1])};
                uint32_t Alo[4] = {lo2(q[2 * t][0]), lo2(q[2 * t + 1][0]),
                                   lo2(q[2 * t][1]), lo2(q[2 * t + 1][1])};
                mma16816h(acc[t], Ahi, b.x, b.y);
                mma16816h(acc[t], Alo, b.x, b.y);
                mma16816h(acc[t], Ahi, b.z, b.w);
            }
        }
    }

    if (kq == 0) {
        float* fx = g_flow + (size_t)(nb * 2) * HW;
        float* fy = fx + HW;
#pragma unroll
        for (int t = 0; t < 2; t++) {
            const int p0 = y * Ww + wm * 32 + t * 16 + nr;
            fx[p0]     = acc[t][0];
            fy[p0]     = acc[t][1];
            fx[p0 + 8] = acc[t][2];
            fy[p0 + 8] = acc[t][3];
        }
    }
}

// ============================================================================
// k4: flow_warp (torch repeat(c,1,1,1) batch-aliasing)
// ============================================================================
__global__ void __launch_bounds__(256) k_warp(
    const float* __restrict__ pred, float* __restrict__ out)
{
    const int idx = blockIdx.x * 256 + threadIdx.x;
    const int x = idx & (Ww - 1);
    const int y = (idx >> 8) & (Hh - 1);
    const int t = idx >> 15;
    const int fb = t & 3;

    const float fx = g_flow[(size_t)(fb * 2 + 0) * HW + y * Ww + x];
    const float fy = g_flow[(size_t)(fb * 2 + 1) * HW + y * Ww + x];

    const float gx = -1.f + 2.f * (float)x / (float)(Ww - 1);
    const float gy = -1.f + 2.f * (float)y / (float)(Hh - 1);
    const float sx = gx + fx / (float)Ww;
    const float sy = gy + fy / (float)Hh;
    const float ix = ((sx + 1.f) * (float)Ww - 1.f) * 0.5f;
    const float iy = ((sy + 1.f) * (float)Hh - 1.f) * 0.5f;

    const float x0f = floorf(ix), y0f = floorf(iy);
    const float wx = ix - x0f, wy = iy - y0f;
    const int x0 = (int)x0f, y0 = (int)y0f;

    const float* img = pred + (size_t)t * HW;
    auto samp = [&](int yy, int xx) -> float {
        return (xx >= 0 && xx < Ww && yy >= 0 && yy < Hh) ? img[yy * Ww + xx] : 0.f;
    };
    const float v00 = samp(y0, x0);
    const float v01 = samp(y0, x0 + 1);
    const float v10 = samp(y0 + 1, x0);
    const float v11 = samp(y0 + 1, x0 + 1);

    const float top = v00 * (1.f - wx) + v01 * wx;
    const float bot = v10 * (1.f - wx) + v11 * wx;
    out[idx] = top * (1.f - wy) + bot * wy;
}

// ============================================================================
// launch
// ============================================================================
extern "C" void kernel_launch(void* const* d_in, const int* in_sizes, int n_in,
                              void* d_out, int out_size)
{
    const float* t1_feature = (const float*)d_in[0];
    const float* t2_feature = (const float*)d_in[1];
    const float* t2_pred    = (const float*)d_in[2];
    const float* w_down1    = (const float*)d_in[3];
    const float* w_down2    = (const float*)d_in[4];
    const float* w_flow1    = (const float*)d_in[5];
    const float* bn_gamma   = (const float*)d_in[6];
    const float* bn_beta    = (const float*)d_in[7];
    const float* bn_mean    = (const float*)d_in[8];
    const float* bn_var     = (const float*)d_in[9];
    const float* w_flow2    = (const float*)d_in[10];
    float* out = (float*)d_out;

    cudaFuncSetAttribute(k2_mma, cudaFuncAttributeMaxDynamicSharedMemorySize, K2_SMEM);

    k_prep<<<217, 256>>>(w_down1, w_down2, w_flow1, w_flow2,
                         bn_gamma, bn_beta, bn_mean, bn_var);
    k1_mma<<<dim3(128, NB, 2), 256, K1_SMEM>>>(t1_feature, t2_feature);
    k_probe<<<1, 32>>>();
    k2_mma<<<dim3(Hh, NB), 256, K2_SMEM>>>();
    k3_mma<<<dim3(Hh, NB), 256>>>();
    k_warp<<<(NB * CCLS * HW) / 256, 256>>>(t2_pred, out);
}

// round 14
// speedup vs baseline: 1.6963x; 1.0475x over previous
#include <cuda_runtime.h>
#include <cuda_fp16.h>
#include <cstdint>

#define Hh 128
#define Ww 256
#define HW (Hh*Ww)
#define NB 4
#define CIN 256
#define Tc 64
#define CCLS 19

// ---------------- scratch (allocation-free: __device__ globals) ----------------
// g_y: [nb][chunk16][pix][8 u32]; u32 = fp16 hi (upper) | fp16 lo (lower) per channel
__device__ __align__(16) uint32_t g_y[NB * 16 * HW * 8];
// g_x2: BN+ReLU output, packed fp16 hi|lo, [nb][chunk8][pix][8 u32]
__device__ __align__(16) uint32_t g_x2[NB * 8 * HW * 8];
__device__ float    g_flow[NB * 2 * HW];      // flow (fp32)
// B fragments (hi only, 2-pass): [..][lane][2] u32 = {hi_reg0, hi_reg1}
__device__ __align__(16) uint32_t g_wd[2 * 16 * 8 * 32 * 2];   // 1x1: [wh][ks16][nf8][lane][2]
__device__ __align__(16) uint32_t g_wf[9 * 8 * 8 * 32 * 2];    // 3x3: [tap][ks8][nf8][lane][2]
// flow-conv B fragments (hi+lo, 3-pass): [tap][ks4][lane][4] = {hi0,hi1,lo0,lo1}
__device__ __align__(16) uint32_t g_wfl[9 * 4 * 32 * 4];
__device__ float    g_bns[64], g_bnb[64];

// k2 staging geometry: [row3][chunk2][px 260][8 u32]; px slot = pixel+1 (0 & 257 zero)
#define ABUF (3 * 2 * 260 * 8)          // u32 per buffer = 12480 (49,920 B)
#define K2_SMEM (2 * ABUF * 4)          // 99,840 B
// k1 staging: [ch16][px 260] fp32 (stride padded for banks)
#define XBUF (16 * 260)                 // floats per buffer (16,640 B)
#define K1_SMEM (2 * XBUF * 4)          // 33,280 B

// ---------------- helpers ----------------
__device__ __forceinline__ uint32_t smem_u32(const void* p) {
    uint32_t a;
    asm("{ .reg .u64 t; cvta.to.shared.u64 t, %1; cvt.u32.u64 %0, t; }" : "=r"(a) : "l"(p));
    return a;
}
__device__ __forceinline__ void cp_async16(uint32_t saddr, const void* g) {
    asm volatile("cp.async.cg.shared.global [%0], [%1], 16;" :: "r"(saddr), "l"(g));
}
__device__ __forceinline__ void cp_async16z(uint32_t saddr, const void* g, int srcsize) {
    asm volatile("cp.async.cg.shared.global [%0], [%1], 16, %2;"
                 :: "r"(saddr), "l"(g), "r"(srcsize));
}
__device__ __forceinline__ void cp_commit() { asm volatile("cp.async.commit_group;"); }
__device__ __forceinline__ void cp_wait0()  { asm volatile("cp.async.wait_group 0;"); }

__device__ __forceinline__ uint32_t split_pack_h(float v) {
    __half h = __float2half_rn(v);
    __half l = __float2half_rn(v - __half2float(h));
    return ((uint32_t)__half_as_ushort(h) << 16) | (uint32_t)__half_as_ushort(l);
}
__device__ __forceinline__ void split2h(float a, float b, uint32_t& hi, uint32_t& lo) {
    __half ha = __float2half_rn(a), hb = __float2half_rn(b);
    __half la = __float2half_rn(a - __half2float(ha));
    __half lb = __float2half_rn(b - __half2float(hb));
    hi = (uint32_t)__half_as_ushort(ha) | ((uint32_t)__half_as_ushort(hb) << 16);
    lo = (uint32_t)__half_as_ushort(la) | ((uint32_t)__half_as_ushort(lb) << 16);
}
__device__ __forceinline__ uint32_t hi2(uint2 v) { return (v.x >> 16) | (v.y & 0xffff0000u); }
__device__ __forceinline__ uint32_t lo2(uint2 v) { return (v.x & 0xffffu) | (v.y << 16); }

__device__ __forceinline__ void mma16816h(float (&c)[4], const uint32_t (&a)[4],
                                          uint32_t b0, uint32_t b1) {
    asm volatile(
        "mma.sync.aligned.m16n8k16.row.col.f32.f16.f16.f32 "
        "{%0,%1,%2,%3},{%4,%5,%6,%7},{%8,%9},{%0,%1,%2,%3};"
        : "+f"(c[0]), "+f"(c[1]), "+f"(c[2]), "+f"(c[3])
        : "r"(a[0]), "r"(a[1]), "r"(a[2]), "r"(a[3]), "r"(b0), "r"(b1));
}

// ============================================================================
// k_prep: weights -> fp16 fragments, BN fold
// ============================================================================
__global__ void __launch_bounds__(256) k_prep(
    const float* __restrict__ w1, const float* __restrict__ w2,
    const float* __restrict__ wf, const float* __restrict__ wfl,
    const float* __restrict__ gamma, const float* __restrict__ beta,
    const float* __restrict__ mean,  const float* __restrict__ var)
{
    int i = blockIdx.x * 256 + threadIdx.x;
    if (i < 64) {
        float s = gamma[i] * rsqrtf(var[i] + 1e-5f);
        g_bns[i] = s;
        g_bnb[i] = beta[i] - mean[i] * s;
    }
    if (i < 2 * 16 * 8 * 32 * 2) {           // 1x1 weights (16384)
        int j    = i & 1;
        int lane = (i >> 1) & 31;
        int nf   = (i >> 6) & 7;
        int ks   = (i >> 9) & 15;
        int wh   = i >> 13;
        int n   = nf * 8 + (lane >> 2);
        int ch0 = ks * 16 + (lane & 3) * 2 + j * 8;
        const float* w = wh ? w2 : w1;
        __half h0 = __float2half_rn(w[n * CIN + ch0]);
        __half h1 = __float2half_rn(w[n * CIN + ch0 + 1]);
        g_wd[(((wh * 16 + ks) * 8 + nf) * 32 + lane) * 2 + j] =
            (uint32_t)__half_as_ushort(h0) | ((uint32_t)__half_as_ushort(h1) << 16);
    }
    int m = i - 2 * 16 * 8 * 32 * 2;
    if (m >= 0 && m < 9 * 8 * 8 * 32 * 2) {  // 3x3 weights (36864)
        int j    = m & 1;
        int lane = (m >> 1) & 31;
        int nf   = (m >> 6) & 7;
        int ks   = (m >> 9) & 7;
        int tap  = m >> 12;
        int n   = nf * 8 + (lane >> 2);
        int ch0 = ks * 16 + (lane & 3) * 2 + j * 8;
        __half h0 = __float2half_rn(wf[n * (128 * 9) + ch0 * 9 + tap]);
        __half h1 = __float2half_rn(wf[n * (128 * 9) + (ch0 + 1) * 9 + tap]);
        g_wf[(((tap * 8 + ks) * 8 + nf) * 32 + lane) * 2 + j] =
            (uint32_t)__half_as_ushort(h0) | ((uint32_t)__half_as_ushort(h1) << 16);
    }
    int p = i - (2 * 16 * 8 * 32 * 2 + 9 * 8 * 8 * 32 * 2);
    if (p >= 0 && p < 9 * 4 * 32 * 2) {      // flow-conv weights (2304), hi+lo
        int j    = p & 1;
        int lane = (p >> 1) & 31;
        int ks   = (p >> 6) & 3;
        int tap  = p >> 8;
        int n   = lane >> 2;                  // only n<2 valid
        int ch0 = ks * 16 + (lane & 3) * 2 + j * 8;
        float v0 = (n < 2) ? wfl[n * 576 + ch0 * 9 + tap] : 0.f;
        float v1 = (n < 2) ? wfl[n * 576 + (ch0 + 1) * 9 + tap] : 0.f;
        uint32_t hi, lo; split2h(v0, v1, hi, lo);
        int base = ((tap * 4 + ks) * 32 + lane) * 4;
        g_wfl[base + j]     = hi;
        g_wfl[base + 2 + j] = lo;
    }
}

// profiler-steering no-op (keeps ncu sampling k2_mma)
__global__ void k_probe() {}

// ============================================================================
// k1: both 1x1 convs, fp16 2-pass mma, cp.async-staged A.
// MMA issue order: pass-outer / nf-inner -> 16 independent accs in flight.
// ============================================================================
__global__ void __launch_bounds__(256, 2) k1_mma(
    const float* __restrict__ x1, const float* __restrict__ x2)
{
    extern __shared__ float sX[];            // [2][16][260] floats
    const int tid = threadIdx.x, lane = tid & 31, wm = tid >> 5;
    const int pt = blockIdx.x, nb = blockIdx.y, wh = blockIdx.z;
    const int kq = lane & 3, nr = lane >> 2;
    const uint32_t sxa = smem_u32(sX);

    const float* X = (wh ? x2 : x1) + (size_t)nb * CIN * HW + pt * 256;
    const uint2* Bw = (const uint2*)g_wd + ((size_t)wh * 16 * 8 * 32 + lane);
    const int base = pt * 256 + wm * 32 + nr;

    float acc[2][8][4];
#pragma unroll
    for (int t = 0; t < 2; t++)
#pragma unroll
        for (int f = 0; f < 8; f++)
#pragma unroll
            for (int q = 0; q < 4; q++) acc[t][f][q] = 0.f;

    auto stage = [&](int ks, int b) {
#pragma unroll
        for (int it = 0; it < 4; it++) {
            int i = tid + it * 256;
            int ch = i >> 6, quad = i & 63;
            const float* src = X + (size_t)(ks * 16 + ch) * HW + quad * 4;
            uint32_t dst = sxa + (uint32_t)(b * XBUF + ch * 260 + quad * 4) * 4u;
            cp_async16(dst, src);
        }
    };

    stage(0, 0);
    cp_commit();

    for (int ks = 0; ks < 16; ks++) {
        cp_wait0();
        __syncthreads();
        if (ks < 15) { stage(ks + 1, (ks + 1) & 1); cp_commit(); }

        const float* buf = sX + (ks & 1) * XBUF;
        uint32_t Ahi[2][4], Alo[2][4];
#pragma unroll
        for (int t = 0; t < 2; t++) {
            const int p0 = wm * 32 + t * 16 + nr, p1 = p0 + 8;
            float f0 = buf[(2 * kq) * 260 + p0],     f1 = buf[(2 * kq + 1) * 260 + p0];
            float f2 = buf[(2 * kq + 8) * 260 + p0], f3 = buf[(2 * kq + 9) * 260 + p0];
            float f4 = buf[(2 * kq) * 260 + p1],     f5 = buf[(2 * kq + 1) * 260 + p1];
            float f6 = buf[(2 * kq + 8) * 260 + p1], f7 = buf[(2 * kq + 9) * 260 + p1];
            split2h(f0, f1, Ahi[t][0], Alo[t][0]);
            split2h(f4, f5, Ahi[t][1], Alo[t][1]);
            split2h(f2, f3, Ahi[t][2], Alo[t][2]);
            split2h(f6, f7, Ahi[t][3], Alo[t][3]);
        }
        // pass-outer, nf-inner: consecutive MMAs hit distinct accumulators
#pragma unroll
        for (int pass = 0; pass < 2; pass++) {
#pragma unroll
            for (int nf = 0; nf < 8; nf++) {
                uint2 b = Bw[(ks * 8 + nf) * 32];
                if (pass == 0) {
                    mma16816h(acc[0][nf], Ahi[0], b.x, b.y);
                    mma16816h(acc[1][nf], Ahi[1], b.x, b.y);
                } else {
                    mma16816h(acc[0][nf], Alo[0], b.x, b.y);
                    mma16816h(acc[1][nf], Alo[1], b.x, b.y);
                }
            }
        }
    }

    // epilogue: pack to g_y [chunk][pix][8]
    uint32_t* gy = g_y + (size_t)nb * 16 * HW * 8;
#pragma unroll
    for (int t = 0; t < 2; t++) {
#pragma unroll
        for (int nf = 0; nf < 8; nf++) {
            const int chunk = wh * 8 + nf;
            const int pA = base + t * 16, pB = pA + 8;
            *(uint2*)&gy[((size_t)chunk * HW + pA) * 8 + 2 * kq] =
                make_uint2(split_pack_h(acc[t][nf][0]), split_pack_h(acc[t][nf][1]));
            *(uint2*)&gy[((size_t)chunk * HW + pB) * 8 + 2 * kq] =
                make_uint2(split_pack_h(acc[t][nf][2]), split_pack_h(acc[t][nf][3]));
        }
    }
}

// ============================================================================
// k2: conv3x3 (128->64) + BN + ReLU, fp16 2-pass mma, cp.async-staged halo.
// MMA issue order: pass-outer / nf-inner -> 16 independent accs in flight.
// ============================================================================
__global__ void __launch_bounds__(256, 2) k2_mma()
{
    extern __shared__ uint32_t sA[];         // [2][3][2][260][8] u32
    const int tid = threadIdx.x, lane = tid & 31, wm = tid >> 5;
    const int y = blockIdx.x, nb = blockIdx.y;
    const int kq = lane & 3, nr = lane >> 2;
    const uint32_t saa = smem_u32(sA);

    float acc[2][8][4];
#pragma unroll
    for (int t = 0; t < 2; t++)
#pragma unroll
        for (int f = 0; f < 8; f++)
#pragma unroll
            for (int q = 0; q < 4; q++) acc[t][f][q] = 0.f;

    // zero the border columns (px slots 0 and 257) of both buffers, once
    for (int i = tid; i < 2 * 6 * 2 * 8; i += 256) {   // 192 words
        int j = i & 7, col = (i >> 3) & 1, rc = (i >> 4) % 6, b = i / 96;
        sA[b * ABUF + (rc * 260 + (col ? 257 : 0)) * 8 + j] = 0u;
    }

    const uint32_t* gyb = g_y + (size_t)nb * 16 * HW * 8;
    const uint2* BwL = (const uint2*)g_wf + lane;

    auto stage = [&](int ks, int b) {
#pragma unroll
        for (int it = 0; it < 12; it++) {
            int i = tid + it * 256;
            int half = i & 1;
            int px = (i >> 1) & 255;
            int rc = i >> 9;                 // 0..5: row*2+chunk
            int row = rc >> 1, chunk = rc & 1;
            int gyr = y + row - 1;
            int ok = ((unsigned)gyr < (unsigned)Hh) ? 16 : 0;
            int gyc = (gyr < 0) ? 0 : (gyr > Hh - 1 ? Hh - 1 : gyr);
            const uint32_t* src = gyb + ((size_t)(2 * ks + chunk) * HW + gyc * Ww + px) * 8 + half * 4;
            uint32_t dst = saa + (uint32_t)(b * ABUF + (rc * 260 + 1 + px) * 8 + half * 4) * 4u;
            cp_async16z(dst, src, ok);
        }
    };

    stage(0, 0);
    cp_commit();

    for (int ks = 0; ks < 8; ks++) {
        cp_wait0();
        __syncthreads();
        if (ks < 7) { stage(ks + 1, (ks + 1) & 1); cp_commit(); }

        const uint32_t* buf = sA + (ks & 1) * ABUF;
#pragma unroll
        for (int tap = 0; tap < 9; tap++) {
            const int row = tap / 3, dx = tap % 3 - 1;
            uint2 q[4][2];
#pragma unroll
            for (int g = 0; g < 4; g++) {
                const int px = wm * 32 + g * 8 + nr + dx + 1;
                q[g][0] = *(const uint2*)&buf[((row * 2 + 0) * 260 + px) * 8 + 2 * kq];
                q[g][1] = *(const uint2*)&buf[((row * 2 + 1) * 260 + px) * 8 + 2 * kq];
            }
            uint32_t Ahi[2][4], Alo[2][4];
#pragma unroll
            for (int t = 0; t < 2; t++) {
                Ahi[t][0] = hi2(q[2 * t][0]);     Alo[t][0] = lo2(q[2 * t][0]);
                Ahi[t][1] = hi2(q[2 * t + 1][0]); Alo[t][1] = lo2(q[2 * t + 1][0]);
                Ahi[t][2] = hi2(q[2 * t][1]);     Alo[t][2] = lo2(q[2 * t][1]);
                Ahi[t][3] = hi2(q[2 * t + 1][1]); Alo[t][3] = lo2(q[2 * t + 1][1]);
            }
            // pass-outer, nf-inner: no back-to-back acc reuse
#pragma unroll
            for (int pass = 0; pass < 2; pass++) {
#pragma unroll
                for (int nf = 0; nf < 8; nf++) {
                    uint2 b = BwL[((tap * 8 + ks) * 8 + nf) * 32];
                    if (pass == 0) {
                        mma16816h(acc[0][nf], Ahi[0], b.x, b.y);
                        mma16816h(acc[1][nf], Ahi[1], b.x, b.y);
                    } else {
                        mma16816h(acc[0][nf], Alo[0], b.x, b.y);
                        mma16816h(acc[1][nf], Alo[1], b.x, b.y);
                    }
                }
            }
        }
    }

    // epilogue: BN + ReLU -> g_x2 packed fp16 hi|lo, [chunk8][pix][8]
    uint32_t* Xo = g_x2 + (size_t)nb * 8 * HW * 8;
#pragma unroll
    for (int t = 0; t < 2; t++) {
        const int op0 = y * Ww + wm * 32 + t * 16 + nr;
        const int op1 = op0 + 8;
#pragma unroll
        for (int nf = 0; nf < 8; nf++) {
            int ch = nf * 8 + 2 * kq;
            float s0 = g_bns[ch], b0 = g_bnb[ch];
            float s1 = g_bns[ch + 1], b1 = g_bnb[ch + 1];
            float r00 = acc[t][nf][0] * s0 + b0; r00 = r00 > 0.f ? r00 : 0.f;
            float r01 = acc[t][nf][1] * s1 + b1; r01 = r01 > 0.f ? r01 : 0.f;
            float r10 = acc[t][nf][2] * s0 + b0; r10 = r10 > 0.f ? r10 : 0.f;
            float r11 = acc[t][nf][3] * s1 + b1; r11 = r11 > 0.f ? r11 : 0.f;
            *(uint2*)&Xo[((size_t)nf * HW + op0) * 8 + 2 * kq] =
                make_uint2(split_pack_h(r00), split_pack_h(r01));
            *(uint2*)&Xo[((size_t)nf * HW + op1) * 8 + 2 * kq] =
                make_uint2(split_pack_h(r10), split_pack_h(r11));
        }
    }
}

// ============================================================================
// k3: conv3x3 (64 -> 2, pad 1) -> flow, via mma (3 passes, pass-outer order).
// ============================================================================
__global__ void __launch_bounds__(256) k3_mma()
{
    const int tid = threadIdx.x, lane = tid & 31, wm = tid >> 5;
    const int y = blockIdx.x, nb = blockIdx.y;
    const int kq = lane & 3, nr = lane >> 2;

    float acc[2][4];
#pragma unroll
    for (int t = 0; t < 2; t++)
#pragma unroll
        for (int q = 0; q < 4; q++) acc[t][q] = 0.f;

    const uint2* Au = (const uint2*)(g_x2 + (size_t)nb * 8 * HW * 8);
    const uint4* BwL = (const uint4*)g_wfl + lane;

#pragma unroll
    for (int tap = 0; tap < 9; tap++) {
        const int dy = tap / 3 - 1, dx = tap % 3 - 1;
        const int gyr = y + dy;
        const bool okY = (unsigned)gyr < (unsigned)Hh;
        int gp[4]; bool vg[4];
#pragma unroll
        for (int g = 0; g < 4; g++) {
            int gx = wm * 32 + g * 8 + nr + dx;
            vg[g] = okY && (unsigned)gx < (unsigned)Ww;
            gp[g] = gyr * Ww + gx;
        }

#pragma unroll
        for (int ks = 0; ks < 4; ks++) {
            const size_t cA = (size_t)(2 * ks) * HW, cB = cA + HW;
            uint2 q[4][2];
#pragma unroll
            for (int g = 0; g < 4; g++) {
                q[g][0] = vg[g] ? Au[(cA + gp[g]) * 4 + kq] : make_uint2(0u, 0u);
                q[g][1] = vg[g] ? Au[(cB + gp[g]) * 4 + kq] : make_uint2(0u, 0u);
            }
            uint4 b = BwL[(tap * 4 + ks) * 32];
            uint32_t Ahi[2][4], Alo[2][4];
#pragma unroll
            for (int t = 0; t < 2; t++) {
                Ahi[t][0] = hi2(q[2 * t][0]); Ahi[t][1] = hi2(q[2 * t + 1][0]);
                Ahi[t][2] = hi2(q[2 * t][1]); Ahi[t][3] = hi2(q[2 * t + 1][1]);
                Alo[t][0] = lo2(q[2 * t][0]); Alo[t][1] = lo2(q[2 * t + 1][0]);
                Alo[t][2] = lo2(q[2 * t][1]); Alo[t][3] = lo2(q[2 * t + 1][1]);
            }
#pragma unroll
            for (int pass = 0; pass < 3; pass++) {
#pragma unroll
                for (int t = 0; t < 2; t++) {
                    if (pass == 0)      mma16816h(acc[t], Ahi[t], b.x, b.y);
                    else if (pass == 1) mma16816h(acc[t], Alo[t], b.x, b.y);
                    else                mma16816h(acc[t], Ahi[t], b.z, b.w);
                }
            }
        }
    }

    if (kq == 0) {
        float* fx = g_flow + (size_t)(nb * 2) * HW;
        float* fy = fx + HW;
#pragma unroll
        for (int t = 0; t < 2; t++) {
            const int p0 = y * Ww + wm * 32 + t * 16 + nr;
            fx[p0]     = acc[t][0];
            fy[p0]     = acc[t][1];
            fx[p0 + 8] = acc[t][2];
            fy[p0 + 8] = acc[t][3];
        }
    }
}

// ============================================================================
// k4: flow_warp (torch repeat(c,1,1,1) batch-aliasing)
// ============================================================================
__global__ void __launch_bounds__(256) k_warp(
    const float* __restrict__ pred, float* __restrict__ out)
{
    const int idx = blockIdx.x * 256 + threadIdx.x;
    const int x = idx & (Ww - 1);
    const int y = (idx >> 8) & (Hh - 1);
    const int t = idx >> 15;
    const int fb = t & 3;

    const float fx = g_flow[(size_t)(fb * 2 + 0) * HW + y * Ww + x];
    const float fy = g_flow[(size_t)(fb * 2 + 1) * HW + y * Ww + x];

    const float gx = -1.f + 2.f * (float)x / (float)(Ww - 1);
    const float gy = -1.f + 2.f * (float)y / (float)(Hh - 1);
    const float sx = gx + fx / (float)Ww;
    const float sy = gy + fy / (float)Hh;
    const float ix = ((sx + 1.f) * (float)Ww - 1.f) * 0.5f;
    const float iy = ((sy + 1.f) * (float)Hh - 1.f) * 0.5f;

    const float x0f = floorf(ix), y0f = floorf(iy);
    const float wx = ix - x0f, wy = iy - y0f;
    const int x0 = (int)x0f, y0 = (int)y0f;

    const float* img = pred + (size_t)t * HW;
    auto samp = [&](int yy, int xx) -> float {
        return (xx >= 0 && xx < Ww && yy >= 0 && yy < Hh) ? img[yy * Ww + xx] : 0.f;
    };
    const float v00 = samp(y0, x0);
    const float v01 = samp(y0, x0 + 1);
    const float v10 = samp(y0 + 1, x0);
    const float v11 = samp(y0 + 1, x0 + 1);

    const float top = v00 * (1.f - wx) + v01 * wx;
    const float bot = v10 * (1.f - wx) + v11 * wx;
    out[idx] = top * (1.f - wy) + bot * wy;
}

// ============================================================================
// launch
// ============================================================================
extern "C" void kernel_launch(void* const* d_in, const int* in_sizes, int n_in,
                              void* d_out, int out_size)
{
    const float* t1_feature = (const float*)d_in[0];
    const float* t2_feature = (const float*)d_in[1];
    const float* t2_pred    = (const float*)d_in[2];
    const float* w_down1    = (const float*)d_in[3];
    const float* w_down2    = (const float*)d_in[4];
    const float* w_flow1    = (const float*)d_in[5];
    const float* bn_gamma   = (const float*)d_in[6];
    const float* bn_beta    = (const float*)d_in[7];
    const float* bn_mean    = (const float*)d_in[8];
    const float* bn_var     = (const float*)d_in[9];
    const float* w_flow2    = (const float*)d_in[10];
    float* out = (float*)d_out;

    cudaFuncSetAttribute(k2_mma, cudaFuncAttributeMaxDynamicSharedMemorySize, K2_SMEM);

    k_prep<<<217, 256>>>(w_down1, w_down2, w_flow1, w_flow2,
                         bn_gamma, bn_beta, bn_mean, bn_var);
    k1_mma<<<dim3(128, NB, 2), 256, K1_SMEM>>>(t1_feature, t2_feature);
    k_probe<<<1, 32>>>();
    k2_mma<<<dim3(Hh, NB), 256, K2_SMEM>>>();
    k3_mma<<<dim3(Hh, NB), 256>>>();
    k_warp<<<(NB * CCLS * HW) / 256, 256>>>(t2_pred, out);
}

// round 15
// speedup vs baseline: 1.6994x; 1.0018x over previous
#include <cuda_runtime.h>
#include <cuda_fp16.h>
#include <cstdint>

#define Hh 128
#define Ww 256
#define HW (Hh*Ww)
#define NB 4
#define CIN 256
#define Tc 64
#define CCLS 19

// ---------------- scratch (allocation-free: __device__ globals) ----------------
// g_y: [nb][chunk16][pix][8 u32]; u32 = fp16 hi (upper) | fp16 lo (lower) per channel
__device__ __align__(16) uint32_t g_y[NB * 16 * HW * 8];
// g_x2: BN+ReLU output, packed fp16 hi|lo, [nb][chunk8][pix][8 u32]
__device__ __align__(16) uint32_t g_x2[NB * 8 * HW * 8];
__device__ float    g_flow[NB * 2 * HW];      // flow (fp32)
// B fragments (hi only, 2-pass): [..][lane][2] u32 = {hi_reg0, hi_reg1}
__device__ __align__(16) uint32_t g_wd[2 * 16 * 8 * 32 * 2];   // 1x1: [wh][ks16][nf8][lane][2]
__device__ __align__(16) uint32_t g_wf[9 * 8 * 8 * 32 * 2];    // 3x3: [tap][ks8][nf8][lane][2]
// flow-conv B fragments (hi+lo, 3-pass): [tap][ks4][lane][4] = {hi0,hi1,lo0,lo1}
__device__ __align__(16) uint32_t g_wfl[9 * 4 * 32 * 4];
__device__ float    g_bns[64], g_bnb[64];

// k2 staging geometry: [row3][chunk2][px 260][8 u32]; px slot = pixel+1 (0 & 257 zero)
#define ABUF (3 * 2 * 260 * 8)          // u32 per buffer = 12480 (49,920 B)
#define K2_SMEM (2 * ABUF * 4)          // 99,840 B
// k1 staging: 2 k-chunks per round: [ch32][px 260] fp32
#define XBUF (32 * 260)                 // floats per buffer (33,280 B)
#define K1_SMEM (2 * XBUF * 4)          // 66,560 B

// ---------------- helpers ----------------
__device__ __forceinline__ uint32_t smem_u32(const void* p) {
    uint32_t a;
    asm("{ .reg .u64 t; cvta.to.shared.u64 t, %1; cvt.u32.u64 %0, t; }" : "=r"(a) : "l"(p));
    return a;
}
__device__ __forceinline__ void cp_async16(uint32_t saddr, const void* g) {
    asm volatile("cp.async.cg.shared.global [%0], [%1], 16;" :: "r"(saddr), "l"(g));
}
__device__ __forceinline__ void cp_async16z(uint32_t saddr, const void* g, int srcsize) {
    asm volatile("cp.async.cg.shared.global [%0], [%1], 16, %2;"
                 :: "r"(saddr), "l"(g), "r"(srcsize));
}
__device__ __forceinline__ void cp_commit() { asm volatile("cp.async.commit_group;"); }
__device__ __forceinline__ void cp_wait0()  { asm volatile("cp.async.wait_group 0;"); }

__device__ __forceinline__ uint32_t split_pack_h(float v) {
    __half h = __float2half_rn(v);
    __half l = __float2half_rn(v - __half2float(h));
    return ((uint32_t)__half_as_ushort(h) << 16) | (uint32_t)__half_as_ushort(l);
}
__device__ __forceinline__ void split2h(float a, float b, uint32_t& hi, uint32_t& lo) {
    __half ha = __float2half_rn(a), hb = __float2half_rn(b);
    __half la = __float2half_rn(a - __half2float(ha));
    __half lb = __float2half_rn(b - __half2float(hb));
    hi = (uint32_t)__half_as_ushort(ha) | ((uint32_t)__half_as_ushort(hb) << 16);
    lo = (uint32_t)__half_as_ushort(la) | ((uint32_t)__half_as_ushort(lb) << 16);
}
__device__ __forceinline__ uint32_t hi2(uint2 v) { return (v.x >> 16) | (v.y & 0xffff0000u); }
__device__ __forceinline__ uint32_t lo2(uint2 v) { return (v.x & 0xffffu) | (v.y << 16); }

__device__ __forceinline__ void mma16816h(float (&c)[4], const uint32_t (&a)[4],
                                          uint32_t b0, uint32_t b1) {
    asm volatile(
        "mma.sync.aligned.m16n8k16.row.col.f32.f16.f16.f32 "
        "{%0,%1,%2,%3},{%4,%5,%6,%7},{%8,%9},{%0,%1,%2,%3};"
        : "+f"(c[0]), "+f"(c[1]), "+f"(c[2]), "+f"(c[3])
        : "r"(a[0]), "r"(a[1]), "r"(a[2]), "r"(a[3]), "r"(b0), "r"(b1));
}

// ============================================================================
// k_prep: weights -> fp16 fragments, BN fold
// ============================================================================
__global__ void __launch_bounds__(256) k_prep(
    const float* __restrict__ w1, const float* __restrict__ w2,
    const float* __restrict__ wf, const float* __restrict__ wfl,
    const float* __restrict__ gamma, const float* __restrict__ beta,
    const float* __restrict__ mean,  const float* __restrict__ var)
{
    int i = blockIdx.x * 256 + threadIdx.x;
    if (i < 64) {
        float s = gamma[i] * rsqrtf(var[i] + 1e-5f);
        g_bns[i] = s;
        g_bnb[i] = beta[i] - mean[i] * s;
    }
    if (i < 2 * 16 * 8 * 32 * 2) {           // 1x1 weights (16384)
        int j    = i & 1;
        int lane = (i >> 1) & 31;
        int nf   = (i >> 6) & 7;
        int ks   = (i >> 9) & 15;
        int wh   = i >> 13;
        int n   = nf * 8 + (lane >> 2);
        int ch0 = ks * 16 + (lane & 3) * 2 + j * 8;
        const float* w = wh ? w2 : w1;
        __half h0 = __float2half_rn(w[n * CIN + ch0]);
        __half h1 = __float2half_rn(w[n * CIN + ch0 + 1]);
        g_wd[(((wh * 16 + ks) * 8 + nf) * 32 + lane) * 2 + j] =
            (uint32_t)__half_as_ushort(h0) | ((uint32_t)__half_as_ushort(h1) << 16);
    }
    int m = i - 2 * 16 * 8 * 32 * 2;
    if (m >= 0 && m < 9 * 8 * 8 * 32 * 2) {  // 3x3 weights (36864)
        int j    = m & 1;
        int lane = (m >> 1) & 31;
        int nf   = (m >> 6) & 7;
        int ks   = (m >> 9) & 7;
        int tap  = m >> 12;
        int n   = nf * 8 + (lane >> 2);
        int ch0 = ks * 16 + (lane & 3) * 2 + j * 8;
        __half h0 = __float2half_rn(wf[n * (128 * 9) + ch0 * 9 + tap]);
        __half h1 = __float2half_rn(wf[n * (128 * 9) + (ch0 + 1) * 9 + tap]);
        g_wf[(((tap * 8 + ks) * 8 + nf) * 32 + lane) * 2 + j] =
            (uint32_t)__half_as_ushort(h0) | ((uint32_t)__half_as_ushort(h1) << 16);
    }
    int p = i - (2 * 16 * 8 * 32 * 2 + 9 * 8 * 8 * 32 * 2);
    if (p >= 0 && p < 9 * 4 * 32 * 2) {      // flow-conv weights (2304), hi+lo
        int j    = p & 1;
        int lane = (p >> 1) & 31;
        int ks   = (p >> 6) & 3;
        int tap  = p >> 8;
        int n   = lane >> 2;                  // only n<2 valid
        int ch0 = ks * 16 + (lane & 3) * 2 + j * 8;
        float v0 = (n < 2) ? wfl[n * 576 + ch0 * 9 + tap] : 0.f;
        float v1 = (n < 2) ? wfl[n * 576 + (ch0 + 1) * 9 + tap] : 0.f;
        uint32_t hi, lo; split2h(v0, v1, hi, lo);
        int base = ((tap * 4 + ks) * 32 + lane) * 4;
        g_wfl[base + j]     = hi;
        g_wfl[base + 2 + j] = lo;
    }
}

// profiler-steering no-op (keeps ncu sampling k2_mma)
__global__ void k_probe() {}

// ============================================================================
// k1: both 1x1 convs, fp16 2-pass mma, cp.async-staged A.
// 2 k-chunks (32 channels) per round: 8 rounds, 64 MMAs/warp between barriers.
// MMA issue order: pass-outer / nf-inner -> 16 independent accs in flight.
// ============================================================================
__global__ void __launch_bounds__(256, 2) k1_mma(
    const float* __restrict__ x1, const float* __restrict__ x2)
{
    extern __shared__ float sX[];            // [2][32][260] floats
    const int tid = threadIdx.x, lane = tid & 31, wm = tid >> 5;
    const int pt = blockIdx.x, nb = blockIdx.y, wh = blockIdx.z;
    const int kq = lane & 3, nr = lane >> 2;
    const uint32_t sxa = smem_u32(sX);

    const float* X = (wh ? x2 : x1) + (size_t)nb * CIN * HW + pt * 256;
    const uint2* Bw = (const uint2*)g_wd + ((size_t)wh * 16 * 8 * 32 + lane);
    const int base = pt * 256 + wm * 32 + nr;

    float acc[2][8][4];
#pragma unroll
    for (int t = 0; t < 2; t++)
#pragma unroll
        for (int f = 0; f < 8; f++)
#pragma unroll
            for (int q = 0; q < 4; q++) acc[t][f][q] = 0.f;

    auto stage = [&](int r, int b) {
#pragma unroll
        for (int it = 0; it < 8; it++) {
            int i = tid + it * 256;
            int ch = i >> 6, quad = i & 63;   // ch 0..31
            const float* src = X + (size_t)(r * 32 + ch) * HW + quad * 4;
            uint32_t dst = sxa + (uint32_t)(b * XBUF + ch * 260 + quad * 4) * 4u;
            cp_async16(dst, src);
        }
    };

    stage(0, 0);
    cp_commit();

    for (int r = 0; r < 8; r++) {
        cp_wait0();
        __syncthreads();
        if (r < 7) { stage(r + 1, (r + 1) & 1); cp_commit(); }

        const float* buf = sX + (r & 1) * XBUF;
#pragma unroll
        for (int ss = 0; ss < 2; ss++) {
            const int ks = 2 * r + ss;
            const float* bc = buf + ss * 16 * 260;
            uint32_t Ahi[2][4], Alo[2][4];
#pragma unroll
            for (int t = 0; t < 2; t++) {
                const int p0 = wm * 32 + t * 16 + nr, p1 = p0 + 8;
                float f0 = bc[(2 * kq) * 260 + p0],     f1 = bc[(2 * kq + 1) * 260 + p0];
                float f2 = bc[(2 * kq + 8) * 260 + p0], f3 = bc[(2 * kq + 9) * 260 + p0];
                float f4 = bc[(2 * kq) * 260 + p1],     f5 = bc[(2 * kq + 1) * 260 + p1];
                float f6 = bc[(2 * kq + 8) * 260 + p1], f7 = bc[(2 * kq + 9) * 260 + p1];
                split2h(f0, f1, Ahi[t][0], Alo[t][0]);
                split2h(f4, f5, Ahi[t][1], Alo[t][1]);
                split2h(f2, f3, Ahi[t][2], Alo[t][2]);
                split2h(f6, f7, Ahi[t][3], Alo[t][3]);
            }
            // pass-outer, nf-inner: consecutive MMAs hit distinct accumulators
#pragma unroll
            for (int pass = 0; pass < 2; pass++) {
#pragma unroll
                for (int nf = 0; nf < 8; nf++) {
                    uint2 b = Bw[(ks * 8 + nf) * 32];
                    if (pass == 0) {
                        mma16816h(acc[0][nf], Ahi[0], b.x, b.y);
                        mma16816h(acc[1][nf], Ahi[1], b.x, b.y);
                    } else {
                        mma16816h(acc[0][nf], Alo[0], b.x, b.y);
                        mma16816h(acc[1][nf], Alo[1], b.x, b.y);
                    }
                }
            }
        }
    }

    // epilogue: pack to g_y [chunk][pix][8]
    uint32_t* gy = g_y + (size_t)nb * 16 * HW * 8;
#pragma unroll
    for (int t = 0; t < 2; t++) {
#pragma unroll
        for (int nf = 0; nf < 8; nf++) {
            const int chunk = wh * 8 + nf;
            const int pA = base + t * 16, pB = pA + 8;
            *(uint2*)&gy[((size_t)chunk * HW + pA) * 8 + 2 * kq] =
                make_uint2(split_pack_h(acc[t][nf][0]), split_pack_h(acc[t][nf][1]));
            *(uint2*)&gy[((size_t)chunk * HW + pB) * 8 + 2 * kq] =
                make_uint2(split_pack_h(acc[t][nf][2]), split_pack_h(acc[t][nf][3]));
        }
    }
}

// ============================================================================
// k2: conv3x3 (128->64) + BN + ReLU, fp16 2-pass mma, cp.async-staged halo.
// MMA issue order: pass-outer / nf-inner -> 16 independent accs in flight.
// ============================================================================
__global__ void __launch_bounds__(256, 2) k2_mma()
{
    extern __shared__ uint32_t sA[];         // [2][3][2][260][8] u32
    const int tid = threadIdx.x, lane = tid & 31, wm = tid >> 5;
    const int y = blockIdx.x, nb = blockIdx.y;
    const int kq = lane & 3, nr = lane >> 2;
    const uint32_t saa = smem_u32(sA);

    float acc[2][8][4];
#pragma unroll
    for (int t = 0; t < 2; t++)
#pragma unroll
        for (int f = 0; f < 8; f++)
#pragma unroll
            for (int q = 0; q < 4; q++) acc[t][f][q] = 0.f;

    // zero the border columns (px slots 0 and 257) of both buffers, once
    for (int i = tid; i < 2 * 6 * 2 * 8; i += 256) {   // 192 words
        int j = i & 7, col = (i >> 3) & 1, rc = (i >> 4) % 6, b = i / 96;
        sA[b * ABUF + (rc * 260 + (col ? 257 : 0)) * 8 + j] = 0u;
    }

    const uint32_t* gyb = g_y + (size_t)nb * 16 * HW * 8;
    const uint2* BwL = (const uint2*)g_wf + lane;

    auto stage = [&](int ks, int b) {
#pragma unroll
        for (int it = 0; it < 12; it++) {
            int i = tid + it * 256;
            int half = i & 1;
            int px = (i >> 1) & 255;
            int rc = i >> 9;                 // 0..5: row*2+chunk
            int row = rc >> 1, chunk = rc & 1;
            int gyr = y + row - 1;
            int ok = ((unsigned)gyr < (unsigned)Hh) ? 16 : 0;
            int gyc = (gyr < 0) ? 0 : (gyr > Hh - 1 ? Hh - 1 : gyr);
            const uint32_t* src = gyb + ((size_t)(2 * ks + chunk) * HW + gyc * Ww + px) * 8 + half * 4;
            uint32_t dst = saa + (uint32_t)(b * ABUF + (rc * 260 + 1 + px) * 8 + half * 4) * 4u;
            cp_async16z(dst, src, ok);
        }
    };

    stage(0, 0);
    cp_commit();

    for (int ks = 0; ks < 8; ks++) {
        cp_wait0();
        __syncthreads();
        if (ks < 7) { stage(ks + 1, (ks + 1) & 1); cp_commit(); }

        const uint32_t* buf = sA + (ks & 1) * ABUF;
#pragma unroll
        for (int tap = 0; tap < 9; tap++) {
            const int row = tap / 3, dx = tap % 3 - 1;
            uint2 q[4][2];
#pragma unroll
            for (int g = 0; g < 4; g++) {
                const int px = wm * 32 + g * 8 + nr + dx + 1;
                q[g][0] = *(const uint2*)&buf[((row * 2 + 0) * 260 + px) * 8 + 2 * kq];
                q[g][1] = *(const uint2*)&buf[((row * 2 + 1) * 260 + px) * 8 + 2 * kq];
            }
            uint32_t Ahi[2][4], Alo[2][4];
#pragma unroll
            for (int t = 0; t < 2; t++) {
                Ahi[t][0] = hi2(q[2 * t][0]);     Alo[t][0] = lo2(q[2 * t][0]);
                Ahi[t][1] = hi2(q[2 * t + 1][0]); Alo[t][1] = lo2(q[2 * t + 1][0]);
                Ahi[t][2] = hi2(q[2 * t][1]);     Alo[t][2] = lo2(q[2 * t][1]);
                Ahi[t][3] = hi2(q[2 * t + 1][1]); Alo[t][3] = lo2(q[2 * t + 1][1]);
            }
            // pass-outer, nf-inner: no back-to-back acc reuse
#pragma unroll
            for (int pass = 0; pass < 2; pass++) {
#pragma unroll
                for (int nf = 0; nf < 8; nf++) {
                    uint2 b = BwL[((tap * 8 + ks) * 8 + nf) * 32];
                    if (pass == 0) {
                        mma16816h(acc[0][nf], Ahi[0], b.x, b.y);
                        mma16816h(acc[1][nf], Ahi[1], b.x, b.y);
                    } else {
                        mma16816h(acc[0][nf], Alo[0], b.x, b.y);
                        mma16816h(acc[1][nf], Alo[1], b.x, b.y);
                    }
                }
            }
        }
    }

    // epilogue: BN + ReLU -> g_x2 packed fp16 hi|lo, [chunk8][pix][8]
    uint32_t* Xo = g_x2 + (size_t)nb * 8 * HW * 8;
#pragma unroll
    for (int t = 0; t < 2; t++) {
        const int op0 = y * Ww + wm * 32 + t * 16 + nr;
        const int op1 = op0 + 8;
#pragma unroll
        for (int nf = 0; nf < 8; nf++) {
            int ch = nf * 8 + 2 * kq;
            float s0 = g_bns[ch], b0 = g_bnb[ch];
            float s1 = g_bns[ch + 1], b1 = g_bnb[ch + 1];
            float r00 = acc[t][nf][0] * s0 + b0; r00 = r00 > 0.f ? r00 : 0.f;
            float r01 = acc[t][nf][1] * s1 + b1; r01 = r01 > 0.f ? r01 : 0.f;
            float r10 = acc[t][nf][2] * s0 + b0; r10 = r10 > 0.f ? r10 : 0.f;
            float r11 = acc[t][nf][3] * s1 + b1; r11 = r11 > 0.f ? r11 : 0.f;
            *(uint2*)&Xo[((size_t)nf * HW + op0) * 8 + 2 * kq] =
                make_uint2(split_pack_h(r00), split_pack_h(r01));
            *(uint2*)&Xo[((size_t)nf * HW + op1) * 8 + 2 * kq] =
                make_uint2(split_pack_h(r10), split_pack_h(r11));
        }
    }
}

// ============================================================================
// k3: conv3x3 (64 -> 2, pad 1) -> flow, via mma (3 passes, pass-outer order).
// ============================================================================
__global__ void __launch_bounds__(256) k3_mma()
{
    const int tid = threadIdx.x, lane = tid & 31, wm = tid >> 5;
    const int y = blockIdx.x, nb = blockIdx.y;
    const int kq = lane & 3, nr = lane >> 2;

    float acc[2][4];
#pragma unroll
    for (int t = 0; t < 2; t++)
#pragma unroll
        for (int q = 0; q < 4; q++) acc[t][q] = 0.f;

    const uint2* Au = (const uint2*)(g_x2 + (size_t)nb * 8 * HW * 8);
    const uint4* BwL = (const uint4*)g_wfl + lane;

#pragma unroll
    for (int tap = 0; tap < 9; tap++) {
        const int dy = tap / 3 - 1, dx = tap % 3 - 1;
        const int gyr = y + dy;
        const bool okY = (unsigned)gyr < (unsigned)Hh;
        int gp[4]; bool vg[4];
#pragma unroll
        for (int g = 0; g < 4; g++) {
            int gx = wm * 32 + g * 8 + nr + dx;
            vg[g] = okY && (unsigned)gx < (unsigned)Ww;
            gp[g] = gyr * Ww + gx;
        }

#pragma unroll
        for (int ks = 0; ks < 4; ks++) {
            const size_t cA = (size_t)(2 * ks) * HW, cB = cA + HW;
            uint2 q[4][2];
#pragma unroll
            for (int g = 0; g < 4; g++) {
                q[g][0] = vg[g] ? Au[(cA + gp[g]) * 4 + kq] : make_uint2(0u, 0u);
                q[g][1] = vg[g] ? Au[(cB + gp[g]) * 4 + kq] : make_uint2(0u, 0u);
            }
            uint4 b = BwL[(tap * 4 + ks) * 32];
            uint32_t Ahi[2][4], Alo[2][4];
#pragma unroll
            for (int t = 0; t < 2; t++) {
                Ahi[t][0] = hi2(q[2 * t][0]); Ahi[t][1] = hi2(q[2 * t + 1][0]);
                Ahi[t][2] = hi2(q[2 * t][1]); Ahi[t][3] = hi2(q[2 * t + 1][1]);
                Alo[t][0] = lo2(q[2 * t][0]); Alo[t][1] = lo2(q[2 * t + 1][0]);
                Alo[t][2] = lo2(q[2 * t][1]); Alo[t][3] = lo2(q[2 * t + 1][1]);
            }
#pragma unroll
            for (int pass = 0; pass < 3; pass++) {
#pragma unroll
                for (int t = 0; t < 2; t++) {
                    if (pass == 0)      mma16816h(acc[t], Ahi[t], b.x, b.y);
                    else if (pass == 1) mma16816h(acc[t], Alo[t], b.x, b.y);
                    else                mma16816h(acc[t], Ahi[t], b.z, b.w);
                }
            }
        }
    }

    if (kq == 0) {
        float* fx = g_flow + (size_t)(nb * 2) * HW;
        float* fy = fx + HW;
#pragma unroll
        for (int t = 0; t < 2; t++) {
            const int p0 = y * Ww + wm * 32 + t * 16 + nr;
            fx[p0]     = acc[t][0];
            fy[p0]     = acc[t][1];
            fx[p0 + 8] = acc[t][2];
            fy[p0 + 8] = acc[t][3];
        }
    }
}

// ============================================================================
// k4: flow_warp (torch repeat(c,1,1,1) batch-aliasing)
// ============================================================================
__global__ void __launch_bounds__(256) k_warp(
    const float* __restrict__ pred, float* __restrict__ out)
{
    const int idx = blockIdx.x * 256 + threadIdx.x;
    const int x = idx & (Ww - 1);
    const int y = (idx >> 8) & (Hh - 1);
    const int t = idx >> 15;
    const int fb = t & 3;

    const float fx = g_flow[(size_t)(fb * 2 + 0) * HW + y * Ww + x];
    const float fy = g_flow[(size_t)(fb * 2 + 1) * HW + y * Ww + x];

    const float gx = -1.f + 2.f * (float)x / (float)(Ww - 1);
    const float gy = -1.f + 2.f * (float)y / (float)(Hh - 1);
    const float sx = gx + fx / (float)Ww;
    const float sy = gy + fy / (float)Hh;
    const float ix = ((sx + 1.f) * (float)Ww - 1.f) * 0.5f;
    const float iy = ((sy + 1.f) * (float)Hh - 1.f) * 0.5f;

    const float x0f = floorf(ix), y0f = floorf(iy);
    const float wx = ix - x0f, wy = iy - y0f;
    const int x0 = (int)x0f, y0 = (int)y0f;

    const float* img = pred + (size_t)t * HW;
    auto samp = [&](int yy, int xx) -> float {
        return (xx >= 0 && xx < Ww && yy >= 0 && yy < Hh) ? img[yy * Ww + xx] : 0.f;
    };
    const float v00 = samp(y0, x0);
    const float v01 = samp(y0, x0 + 1);
    const float v10 = samp(y0 + 1, x0);
    const float v11 = samp(y0 + 1, x0 + 1);

    const float top = v00 * (1.f - wx) + v01 * wx;
    const float bot = v10 * (1.f - wx) + v11 * wx;
    out[idx] = top * (1.f - wy) + bot * wy;
}

// ============================================================================
// launch
// ============================================================================
extern "C" void kernel_launch(void* const* d_in, const int* in_sizes, int n_in,
                              void* d_out, int out_size)
{
    const float* t1_feature = (const float*)d_in[0];
    const float* t2_feature = (const float*)d_in[1];
    const float* t2_pred    = (const float*)d_in[2];
    const float* w_down1    = (const float*)d_in[3];
    const float* w_down2    = (const float*)d_in[4];
    const float* w_flow1    = (const float*)d_in[5];
    const float* bn_gamma   = (const float*)d_in[6];
    const float* bn_beta    = (const float*)d_in[7];
    const float* bn_mean    = (const float*)d_in[8];
    const float* bn_var     = (const float*)d_in[9];
    const float* w_flow2    = (const float*)d_in[10];
    float* out = (float*)d_out;

    cudaFuncSetAttribute(k1_mma, cudaFuncAttributeMaxDynamicSharedMemorySize, K1_SMEM);
    cudaFuncSetAttribute(k2_mma, cudaFuncAttributeMaxDynamicSharedMemorySize, K2_SMEM);

    k_prep<<<217, 256>>>(w_down1, w_down2, w_flow1, w_flow2,
                         bn_gamma, bn_beta, bn_mean, bn_var);
    k1_mma<<<dim3(128, NB, 2), 256, K1_SMEM>>>(t1_feature, t2_feature);
    k_probe<<<1, 32>>>();
    k2_mma<<<dim3(Hh, NB), 256, K2_SMEM>>>();
    k3_mma<<<dim3(Hh, NB), 256>>>();
    k_warp<<<(NB * CCLS * HW) / 256, 256>>>(t2_pred, out);
}

// round 16
// speedup vs baseline: 2.2177x; 1.3050x over previous
#include <cuda_runtime.h>
#include <cuda_fp16.h>
#include <cstdint>

#define Hh 128
#define Ww 256
#define HW (Hh*Ww)
#define NB 4
#define CIN 256
#define Tc 64
#define CCLS 19

// ---------------- scratch (allocation-free: __device__ globals) ----------------
// g_y: [nb][chunk16][pix][8 u32]; u32 = fp16 hi (upper) | fp16 lo (lower) per channel
__device__ __align__(16) uint32_t g_y[NB * 16 * HW * 8];
// g_x2: BN+ReLU output, packed fp16 hi|lo, [nb][chunk8][pix][8 u32]
__device__ __align__(16) uint32_t g_x2[NB * 8 * HW * 8];
__device__ float    g_flow[NB * 2 * HW];      // flow (fp32)
// B fragments (hi only): [..][lane][2] u32 = {hi_reg0, hi_reg1}
__device__ __align__(16) uint32_t g_wd[2 * 16 * 8 * 32 * 2];   // 1x1: [wh][ks16][nf8][lane][2]
__device__ __align__(16) uint32_t g_wf[9 * 8 * 8 * 32 * 2];    // 3x3: [tap][ks8][nf8][lane][2]
// flow-conv B fragments (hi+lo, 3-pass): [tap][ks4][lane][4] = {hi0,hi1,lo0,lo1}
__device__ __align__(16) uint32_t g_wfl[9 * 4 * 32 * 4];
__device__ float    g_bns[64], g_bnb[64];

// k2 staging geometry: [row3][chunk2][px 260][8 u32]; px slot = pixel+1 (0 & 257 zero)
#define ABUF (3 * 2 * 260 * 8)          // u32 per buffer = 12480 (49,920 B)
#define K2_SMEM (2 * ABUF * 4)          // 99,840 B
// k1 staging: 2 k-chunks per round: [ch32][px 260] fp32
#define XBUF (32 * 260)                 // floats per buffer (33,280 B)
#define K1_SMEM (2 * XBUF * 4)          // 66,560 B

// ---------------- helpers ----------------
__device__ __forceinline__ uint32_t smem_u32(const void* p) {
    uint32_t a;
    asm("{ .reg .u64 t; cvta.to.shared.u64 t, %1; cvt.u32.u64 %0, t; }" : "=r"(a) : "l"(p));
    return a;
}
__device__ __forceinline__ void cp_async16(uint32_t saddr, const void* g) {
    asm volatile("cp.async.cg.shared.global [%0], [%1], 16;" :: "r"(saddr), "l"(g));
}
__device__ __forceinline__ void cp_async16z(uint32_t saddr, const void* g, int srcsize) {
    asm volatile("cp.async.cg.shared.global [%0], [%1], 16, %2;"
                 :: "r"(saddr), "l"(g), "r"(srcsize));
}
__device__ __forceinline__ void cp_commit() { asm volatile("cp.async.commit_group;"); }
__device__ __forceinline__ void cp_wait0()  { asm volatile("cp.async.wait_group 0;"); }

__device__ __forceinline__ uint32_t split_pack_h(float v) {
    __half h = __float2half_rn(v);
    __half l = __float2half_rn(v - __half2float(h));
    return ((uint32_t)__half_as_ushort(h) << 16) | (uint32_t)__half_as_ushort(l);
}
__device__ __forceinline__ void split2h(float a, float b, uint32_t& hi, uint32_t& lo) {
    __half ha = __float2half_rn(a), hb = __float2half_rn(b);
    __half la = __float2half_rn(a - __half2float(ha));
    __half lb = __float2half_rn(b - __half2float(hb));
    hi = (uint32_t)__half_as_ushort(ha) | ((uint32_t)__half_as_ushort(hb) << 16);
    lo = (uint32_t)__half_as_ushort(la) | ((uint32_t)__half_as_ushort(lb) << 16);
}
// hi-only pack of two fp32 -> fp16x2 (1-pass A fragment)
__device__ __forceinline__ uint32_t pack2hi(float a, float b) {
    __half ha = __float2half_rn(a), hb = __float2half_rn(b);
    return (uint32_t)__half_as_ushort(ha) | ((uint32_t)__half_as_ushort(hb) << 16);
}
__device__ __forceinline__ uint32_t hi2(uint2 v) { return (v.x >> 16) | (v.y & 0xffff0000u); }
__device__ __forceinline__ uint32_t lo2(uint2 v) { return (v.x & 0xffffu) | (v.y << 16); }

__device__ __forceinline__ void mma16816h(float (&c)[4], const uint32_t (&a)[4],
                                          uint32_t b0, uint32_t b1) {
    asm volatile(
        "mma.sync.aligned.m16n8k16.row.col.f32.f16.f16.f32 "
        "{%0,%1,%2,%3},{%4,%5,%6,%7},{%8,%9},{%0,%1,%2,%3};"
        : "+f"(c[0]), "+f"(c[1]), "+f"(c[2]), "+f"(c[3])
        : "r"(a[0]), "r"(a[1]), "r"(a[2]), "r"(a[3]), "r"(b0), "r"(b1));
}

// ============================================================================
// k_prep: weights -> fp16 fragments, BN fold
// ============================================================================
__global__ void __launch_bounds__(256) k_prep(
    const float* __restrict__ w1, const float* __restrict__ w2,
    const float* __restrict__ wf, const float* __restrict__ wfl,
    const float* __restrict__ gamma, const float* __restrict__ beta,
    const float* __restrict__ mean,  const float* __restrict__ var)
{
    int i = blockIdx.x * 256 + threadIdx.x;
    if (i < 64) {
        float s = gamma[i] * rsqrtf(var[i] + 1e-5f);
        g_bns[i] = s;
        g_bnb[i] = beta[i] - mean[i] * s;
    }
    if (i < 2 * 16 * 8 * 32 * 2) {           // 1x1 weights (16384)
        int j    = i & 1;
        int lane = (i >> 1) & 31;
        int nf   = (i >> 6) & 7;
        int ks   = (i >> 9) & 15;
        int wh   = i >> 13;
        int n   = nf * 8 + (lane >> 2);
        int ch0 = ks * 16 + (lane & 3) * 2 + j * 8;
        const float* w = wh ? w2 : w1;
        __half h0 = __float2half_rn(w[n * CIN + ch0]);
        __half h1 = __float2half_rn(w[n * CIN + ch0 + 1]);
        g_wd[(((wh * 16 + ks) * 8 + nf) * 32 + lane) * 2 + j] =
            (uint32_t)__half_as_ushort(h0) | ((uint32_t)__half_as_ushort(h1) << 16);
    }
    int m = i - 2 * 16 * 8 * 32 * 2;
    if (m >= 0 && m < 9 * 8 * 8 * 32 * 2) {  // 3x3 weights (36864)
        int j    = m & 1;
        int lane = (m >> 1) & 31;
        int nf   = (m >> 6) & 7;
        int ks   = (m >> 9) & 7;
        int tap  = m >> 12;
        int n   = nf * 8 + (lane >> 2);
        int ch0 = ks * 16 + (lane & 3) * 2 + j * 8;
        __half h0 = __float2half_rn(wf[n * (128 * 9) + ch0 * 9 + tap]);
        __half h1 = __float2half_rn(wf[n * (128 * 9) + (ch0 + 1) * 9 + tap]);
        g_wf[(((tap * 8 + ks) * 8 + nf) * 32 + lane) * 2 + j] =
            (uint32_t)__half_as_ushort(h0) | ((uint32_t)__half_as_ushort(h1) << 16);
    }
    int p = i - (2 * 16 * 8 * 32 * 2 + 9 * 8 * 8 * 32 * 2);
    if (p >= 0 && p < 9 * 4 * 32 * 2) {      // flow-conv weights (2304), hi+lo
        int j    = p & 1;
        int lane = (p >> 1) & 31;
        int ks   = (p >> 6) & 3;
        int tap  = p >> 8;
        int n   = lane >> 2;                  // only n<2 valid
        int ch0 = ks * 16 + (lane & 3) * 2 + j * 8;
        float v0 = (n < 2) ? wfl[n * 576 + ch0 * 9 + tap] : 0.f;
        float v1 = (n < 2) ? wfl[n * 576 + (ch0 + 1) * 9 + tap] : 0.f;
        uint32_t hi, lo; split2h(v0, v1, hi, lo);
        int base = ((tap * 4 + ks) * 32 + lane) * 4;
        g_wfl[base + j]     = hi;
        g_wfl[base + 2 + j] = lo;
    }
}

// profiler-steering no-op (keeps ncu sampling k2_mma)
__global__ void k_probe() {}

// ============================================================================
// k1: both 1x1 convs, fp16 SINGLE-pass mma (A hi only), cp.async-staged A.
// 2 k-chunks per round; 8 independent accumulator targets per pass.
// ============================================================================
__global__ void __launch_bounds__(256, 2) k1_mma(
    const float* __restrict__ x1, const float* __restrict__ x2)
{
    extern __shared__ float sX[];            // [2][32][260] floats
    const int tid = threadIdx.x, lane = tid & 31, wm = tid >> 5;
    const int pt = blockIdx.x, nb = blockIdx.y, wh = blockIdx.z;
    const int kq = lane & 3, nr = lane >> 2;
    const uint32_t sxa = smem_u32(sX);

    const float* X = (wh ? x2 : x1) + (size_t)nb * CIN * HW + pt * 256;
    const uint2* Bw = (const uint2*)g_wd + ((size_t)wh * 16 * 8 * 32 + lane);
    const int base = pt * 256 + wm * 32 + nr;

    float acc[2][8][4];
#pragma unroll
    for (int t = 0; t < 2; t++)
#pragma unroll
        for (int f = 0; f < 8; f++)
#pragma unroll
            for (int q = 0; q < 4; q++) acc[t][f][q] = 0.f;

    auto stage = [&](int r, int b) {
#pragma unroll
        for (int it = 0; it < 8; it++) {
            int i = tid + it * 256;
            int ch = i >> 6, quad = i & 63;   // ch 0..31
            const float* src = X + (size_t)(r * 32 + ch) * HW + quad * 4;
            uint32_t dst = sxa + (uint32_t)(b * XBUF + ch * 260 + quad * 4) * 4u;
            cp_async16(dst, src);
        }
    };

    stage(0, 0);
    cp_commit();

    for (int r = 0; r < 8; r++) {
        cp_wait0();
        __syncthreads();
        if (r < 7) { stage(r + 1, (r + 1) & 1); cp_commit(); }

        const float* buf = sX + (r & 1) * XBUF;
#pragma unroll
        for (int ss = 0; ss < 2; ss++) {
            const int ks = 2 * r + ss;
            const float* bc = buf + ss * 16 * 260;
            uint32_t Ahi[2][4];
#pragma unroll
            for (int t = 0; t < 2; t++) {
                const int p0 = wm * 32 + t * 16 + nr, p1 = p0 + 8;
                Ahi[t][0] = pack2hi(bc[(2 * kq) * 260 + p0],     bc[(2 * kq + 1) * 260 + p0]);
                Ahi[t][1] = pack2hi(bc[(2 * kq) * 260 + p1],     bc[(2 * kq + 1) * 260 + p1]);
                Ahi[t][2] = pack2hi(bc[(2 * kq + 8) * 260 + p0], bc[(2 * kq + 9) * 260 + p0]);
                Ahi[t][3] = pack2hi(bc[(2 * kq + 8) * 260 + p1], bc[(2 * kq + 9) * 260 + p1]);
            }
#pragma unroll
            for (int nf = 0; nf < 8; nf++) {
                uint2 b = Bw[(ks * 8 + nf) * 32];
                mma16816h(acc[0][nf], Ahi[0], b.x, b.y);
                mma16816h(acc[1][nf], Ahi[1], b.x, b.y);
            }
        }
    }

    // epilogue: pack to g_y [chunk][pix][8]
    uint32_t* gy = g_y + (size_t)nb * 16 * HW * 8;
#pragma unroll
    for (int t = 0; t < 2; t++) {
#pragma unroll
        for (int nf = 0; nf < 8; nf++) {
            const int chunk = wh * 8 + nf;
            const int pA = base + t * 16, pB = pA + 8;
            *(uint2*)&gy[((size_t)chunk * HW + pA) * 8 + 2 * kq] =
                make_uint2(split_pack_h(acc[t][nf][0]), split_pack_h(acc[t][nf][1]));
            *(uint2*)&gy[((size_t)chunk * HW + pB) * 8 + 2 * kq] =
                make_uint2(split_pack_h(acc[t][nf][2]), split_pack_h(acc[t][nf][3]));
        }
    }
}

// ============================================================================
// k2: conv3x3 (128->64) + BN + ReLU, fp16 SINGLE-pass mma (A hi only),
// cp.async-staged halo. Epilogue writes packed fp16 g_x2 (hi+lo for k3).
// ============================================================================
__global__ void __launch_bounds__(256, 2) k2_mma()
{
    extern __shared__ uint32_t sA[];         // [2][3][2][260][8] u32
    const int tid = threadIdx.x, lane = tid & 31, wm = tid >> 5;
    const int y = blockIdx.x, nb = blockIdx.y;
    const int kq = lane & 3, nr = lane >> 2;
    const uint32_t saa = smem_u32(sA);

    float acc[2][8][4];
#pragma unroll
    for (int t = 0; t < 2; t++)
#pragma unroll
        for (int f = 0; f < 8; f++)
#pragma unroll
            for (int q = 0; q < 4; q++) acc[t][f][q] = 0.f;

    // zero the border columns (px slots 0 and 257) of both buffers, once
    for (int i = tid; i < 2 * 6 * 2 * 8; i += 256) {   // 192 words
        int j = i & 7, col = (i >> 3) & 1, rc = (i >> 4) % 6, b = i / 96;
        sA[b * ABUF + (rc * 260 + (col ? 257 : 0)) * 8 + j] = 0u;
    }

    const uint32_t* gyb = g_y + (size_t)nb * 16 * HW * 8;
    const uint2* BwL = (const uint2*)g_wf + lane;

    auto stage = [&](int ks, int b) {
#pragma unroll
        for (int it = 0; it < 12; it++) {
            int i = tid + it * 256;
            int half = i & 1;
            int px = (i >> 1) & 255;
            int rc = i >> 9;                 // 0..5: row*2+chunk
            int row = rc >> 1, chunk = rc & 1;
            int gyr = y + row - 1;
            int ok = ((unsigned)gyr < (unsigned)Hh) ? 16 : 0;
            int gyc = (gyr < 0) ? 0 : (gyr > Hh - 1 ? Hh - 1 : gyr);
            const uint32_t* src = gyb + ((size_t)(2 * ks + chunk) * HW + gyc * Ww + px) * 8 + half * 4;
            uint32_t dst = saa + (uint32_t)(b * ABUF + (rc * 260 + 1 + px) * 8 + half * 4) * 4u;
            cp_async16z(dst, src, ok);
        }
    };

    stage(0, 0);
    cp_commit();

    for (int ks = 0; ks < 8; ks++) {
        cp_wait0();
        __syncthreads();
        if (ks < 7) { stage(ks + 1, (ks + 1) & 1); cp_commit(); }

        const uint32_t* buf = sA + (ks & 1) * ABUF;
#pragma unroll
        for (int tap = 0; tap < 9; tap++) {
            const int row = tap / 3, dx = tap % 3 - 1;
            uint2 q[4][2];
#pragma unroll
            for (int g = 0; g < 4; g++) {
                const int px = wm * 32 + g * 8 + nr + dx + 1;
                q[g][0] = *(const uint2*)&buf[((row * 2 + 0) * 260 + px) * 8 + 2 * kq];
                q[g][1] = *(const uint2*)&buf[((row * 2 + 1) * 260 + px) * 8 + 2 * kq];
            }
            uint32_t Ahi[2][4];
#pragma unroll
            for (int t = 0; t < 2; t++) {
                Ahi[t][0] = hi2(q[2 * t][0]);
                Ahi[t][1] = hi2(q[2 * t + 1][0]);
                Ahi[t][2] = hi2(q[2 * t][1]);
                Ahi[t][3] = hi2(q[2 * t + 1][1]);
            }
#pragma unroll
            for (int nf = 0; nf < 8; nf++) {
                uint2 b = BwL[((tap * 8 + ks) * 8 + nf) * 32];
                mma16816h(acc[0][nf], Ahi[0], b.x, b.y);
                mma16816h(acc[1][nf], Ahi[1], b.x, b.y);
            }
        }
    }

    // epilogue: BN + ReLU -> g_x2 packed fp16 hi|lo, [chunk8][pix][8]
    uint32_t* Xo = g_x2 + (size_t)nb * 8 * HW * 8;
#pragma unroll
    for (int t = 0; t < 2; t++) {
        const int op0 = y * Ww + wm * 32 + t * 16 + nr;
        const int op1 = op0 + 8;
#pragma unroll
        for (int nf = 0; nf < 8; nf++) {
            int ch = nf * 8 + 2 * kq;
            float s0 = g_bns[ch], b0 = g_bnb[ch];
            float s1 = g_bns[ch + 1], b1 = g_bnb[ch + 1];
            float r00 = acc[t][nf][0] * s0 + b0; r00 = r00 > 0.f ? r00 : 0.f;
            float r01 = acc[t][nf][1] * s1 + b1; r01 = r01 > 0.f ? r01 : 0.f;
            float r10 = acc[t][nf][2] * s0 + b0; r10 = r10 > 0.f ? r10 : 0.f;
            float r11 = acc[t][nf][3] * s1 + b1; r11 = r11 > 0.f ? r11 : 0.f;
            *(uint2*)&Xo[((size_t)nf * HW + op0) * 8 + 2 * kq] =
                make_uint2(split_pack_h(r00), split_pack_h(r01));
            *(uint2*)&Xo[((size_t)nf * HW + op1) * 8 + 2 * kq] =
                make_uint2(split_pack_h(r10), split_pack_h(r11));
        }
    }
}

// ============================================================================
// k3: conv3x3 (64 -> 2, pad 1) -> flow, via mma (3 passes, pass-outer order).
// ============================================================================
__global__ void __launch_bounds__(256) k3_mma()
{
    const int tid = threadIdx.x, lane = tid & 31, wm = tid >> 5;
    const int y = blockIdx.x, nb = blockIdx.y;
    const int kq = lane & 3, nr = lane >> 2;

    float acc[2][4];
#pragma unroll
    for (int t = 0; t < 2; t++)
#pragma unroll
        for (int q = 0; q < 4; q++) acc[t][q] = 0.f;

    const uint2* Au = (const uint2*)(g_x2 + (size_t)nb * 8 * HW * 8);
    const uint4* BwL = (const uint4*)g_wfl + lane;

#pragma unroll
    for (int tap = 0; tap < 9; tap++) {
        const int dy = tap / 3 - 1, dx = tap % 3 - 1;
        const int gyr = y + dy;
        const bool okY = (unsigned)gyr < (unsigned)Hh;
        int gp[4]; bool vg[4];
#pragma unroll
        for (int g = 0; g < 4; g++) {
            int gx = wm * 32 + g * 8 + nr + dx;
            vg[g] = okY && (unsigned)gx < (unsigned)Ww;
            gp[g] = gyr * Ww + gx;
        }

#pragma unroll
        for (int ks = 0; ks < 4; ks++) {
            const size_t cA = (size_t)(2 * ks) * HW, cB = cA + HW;
            uint2 q[4][2];
#pragma unroll
            for (int g = 0; g < 4; g++) {
                q[g][0] = vg[g] ? Au[(cA + gp[g]) * 4 + kq] : make_uint2(0u, 0u);
                q[g][1] = vg[g] ? Au[(cB + gp[g]) * 4 + kq] : make_uint2(0u, 0u);
            }
            uint4 b = BwL[(tap * 4 + ks) * 32];
            uint32_t Ahi[2][4], Alo[2][4];
#pragma unroll
            for (int t = 0; t < 2; t++) {
                Ahi[t][0] = hi2(q[2 * t][0]); Ahi[t][1] = hi2(q[2 * t + 1][0]);
                Ahi[t][2] = hi2(q[2 * t][1]); Ahi[t][3] = hi2(q[2 * t + 1][1]);
                Alo[t][0] = lo2(q[2 * t][0]); Alo[t][1] = lo2(q[2 * t + 1][0]);
                Alo[t][2] = lo2(q[2 * t][1]); Alo[t][3] = lo2(q[2 * t + 1][1]);
            }
#pragma unroll
            for (int pass = 0; pass < 3; pass++) {
#pragma unroll
                for (int t = 0; t < 2; t++) {
                    if (pass == 0)      mma16816h(acc[t], Ahi[t], b.x, b.y);
                    else if (pass == 1) mma16816h(acc[t], Alo[t], b.x, b.y);
                    else                mma16816h(acc[t], Ahi[t], b.z, b.w);
                }
            }
        }
    }

    if (kq == 0) {
        float* fx = g_flow + (size_t)(nb * 2) * HW;
        float* fy = fx + HW;
#pragma unroll
        for (int t = 0; t < 2; t++) {
            const int p0 = y * Ww + wm * 32 + t * 16 + nr;
            fx[p0]     = acc[t][0];
            fy[p0]     = acc[t][1];
            fx[p0 + 8] = acc[t][2];
            fy[p0 + 8] = acc[t][3];
        }
    }
}

// ============================================================================
// k4: flow_warp (torch repeat(c,1,1,1) batch-aliasing)
// ============================================================================
__global__ void __launch_bounds__(256) k_warp(
    const float* __restrict__ pred, float* __restrict__ out)
{
    const int idx = blockIdx.x * 256 + threadIdx.x;
    const int x = idx & (Ww - 1);
    const int y = (idx >> 8) & (Hh - 1);
    const int t = idx >> 15;
    const int fb = t & 3;

    const float fx = g_flow[(size_t)(fb * 2 + 0) * HW + y * Ww + x];
    const float fy = g_flow[(size_t)(fb * 2 + 1) * HW + y * Ww + x];

    const float gx = -1.f + 2.f * (float)x / (float)(Ww - 1);
    const float gy = -1.f + 2.f * (float)y / (float)(Hh - 1);
    const float sx = gx + fx / (float)Ww;
    const float sy = gy + fy / (float)Hh;
    const float ix = ((sx + 1.f) * (float)Ww - 1.f) * 0.5f;
    const float iy = ((sy + 1.f) * (float)Hh - 1.f) * 0.5f;

    const float x0f = floorf(ix), y0f = floorf(iy);
    const float wx = ix - x0f, wy = iy - y0f;
    const int x0 = (int)x0f, y0 = (int)y0f;

    const float* img = pred + (size_t)t * HW;
    auto samp = [&](int yy, int xx) -> float {
        return (xx >= 0 && xx < Ww && yy >= 0 && yy < Hh) ? img[yy * Ww + xx] : 0.f;
    };
    const float v00 = samp(y0, x0);
    const float v01 = samp(y0, x0 + 1);
    const float v10 = samp(y0 + 1, x0);
    const float v11 = samp(y0 + 1, x0 + 1);

    const float top = v00 * (1.f - wx) + v01 * wx;
    const float bot = v10 * (1.f - wx) + v11 * wx;
    out[idx] = top * (1.f - wy) + bot * wy;
}

// ============================================================================
// launch
// ============================================================================
extern "C" void kernel_launch(void* const* d_in, const int* in_sizes, int n_in,
                              void* d_out, int out_size)
{
    const float* t1_feature = (const float*)d_in[0];
    const float* t2_feature = (const float*)d_in[1];
    const float* t2_pred    = (const float*)d_in[2];
    const float* w_down1    = (const float*)d_in[3];
    const float* w_down2    = (const float*)d_in[4];
    const float* w_flow1    = (const float*)d_in[5];
    const float* bn_gamma   = (const float*)d_in[6];
    const float* bn_beta    = (const float*)d_in[7];
    const float* bn_mean    = (const float*)d_in[8];
    const float* bn_var     = (const float*)d_in[9];
    const float* w_flow2    = (const float*)d_in[10];
    float* out = (float*)d_out;

    cudaFuncSetAttribute(k1_mma, cudaFuncAttributeMaxDynamicSharedMemorySize, K1_SMEM);
    cudaFuncSetAttribute(k2_mma, cudaFuncAttributeMaxDynamicSharedMemorySize, K2_SMEM);

    k_prep<<<217, 256>>>(w_down1, w_down2, w_flow1, w_flow2,
                         bn_gamma, bn_beta, bn_mean, bn_var);
    k1_mma<<<dim3(128, NB, 2), 256, K1_SMEM>>>(t1_feature, t2_feature);
    k_probe<<<1, 32>>>();
    k2_mma<<<dim3(Hh, NB), 256, K2_SMEM>>>();
    k3_mma<<<dim3(Hh, NB), 256>>>();
    k_warp<<<(NB * CCLS * HW) / 256, 256>>>(t2_pred, out);
}

// round 17
// speedup vs baseline: 2.3982x; 1.0814x over previous
#include <cuda_runtime.h>
#include <cuda_fp16.h>
#include <cstdint>

#define Hh 128
#define Ww 256
#define HW (Hh*Ww)
#define NB 4
#define CIN 256
#define Tc 64
#define CCLS 19

// ---------------- scratch (allocation-free: __device__ globals) ----------------
// g_y: fp16 HI only: [nb][chunk16][pix][4 u32]; u32 j = {ch2j, ch2j+1} fp16x2
__device__ __align__(16) uint32_t g_y[NB * 16 * HW * 4];
// g_x2: BN+ReLU output, packed fp16 hi|lo (k3 needs lo), [nb][chunk8][pix][8 u32]
__device__ __align__(16) uint32_t g_x2[NB * 8 * HW * 8];
__device__ float    g_flow[NB * 2 * HW];      // flow (fp32)
// B fragments (hi only): [..][lane][2] u32 = {hi_reg0, hi_reg1}
__device__ __align__(16) uint32_t g_wd[2 * 16 * 8 * 32 * 2];   // 1x1: [wh][ks16][nf8][lane][2]
__device__ __align__(16) uint32_t g_wf[9 * 8 * 8 * 32 * 2];    // 3x3: [tap][ks8][nf8][lane][2]
// flow-conv B fragments (hi+lo, 3-pass): [tap][ks4][lane][4] = {hi0,hi1,lo0,lo1}
__device__ __align__(16) uint32_t g_wfl[9 * 4 * 32 * 4];
__device__ float    g_bns[64], g_bnb[64];

// k2 staging geometry: [row3][chunk2][px 260][4 u32]; px slot = pixel+1 (0 & 257 zero)
#define ABUF (3 * 2 * 260 * 4)          // u32 per buffer = 6240 (24,960 B)
#define K2_SMEM (2 * ABUF * 4)          // 49,920 B
// k1 staging: 2 k-chunks per round: [ch32][px 260] fp32
#define XBUF (32 * 260)                 // floats per buffer (33,280 B)
#define K1_SMEM (2 * XBUF * 4)          // 66,560 B

// ---------------- helpers ----------------
__device__ __forceinline__ uint32_t smem_u32(const void* p) {
    uint32_t a;
    asm("{ .reg .u64 t; cvta.to.shared.u64 t, %1; cvt.u32.u64 %0, t; }" : "=r"(a) : "l"(p));
    return a;
}
__device__ __forceinline__ void cp_async16(uint32_t saddr, const void* g) {
    asm volatile("cp.async.cg.shared.global [%0], [%1], 16;" :: "r"(saddr), "l"(g));
}
__device__ __forceinline__ void cp_async16z(uint32_t saddr, const void* g, int srcsize) {
    asm volatile("cp.async.cg.shared.global [%0], [%1], 16, %2;"
                 :: "r"(saddr), "l"(g), "r"(srcsize));
}
__device__ __forceinline__ void cp_commit() { asm volatile("cp.async.commit_group;"); }
__device__ __forceinline__ void cp_wait0()  { asm volatile("cp.async.wait_group 0;"); }

__device__ __forceinline__ uint32_t split_pack_h(float v) {
    __half h = __float2half_rn(v);
    __half l = __float2half_rn(v - __half2float(h));
    return ((uint32_t)__half_as_ushort(h) << 16) | (uint32_t)__half_as_ushort(l);
}
__device__ __forceinline__ void split2h(float a, float b, uint32_t& hi, uint32_t& lo) {
    __half ha = __float2half_rn(a), hb = __float2half_rn(b);
    __half la = __float2half_rn(a - __half2float(ha));
    __half lb = __float2half_rn(b - __half2float(hb));
    hi = (uint32_t)__half_as_ushort(ha) | ((uint32_t)__half_as_ushort(hb) << 16);
    lo = (uint32_t)__half_as_ushort(la) | ((uint32_t)__half_as_ushort(lb) << 16);
}
// hi-only pack of two fp32 -> fp16x2
__device__ __forceinline__ uint32_t pack2hi(float a, float b) {
    __half ha = __float2half_rn(a), hb = __float2half_rn(b);
    return (uint32_t)__half_as_ushort(ha) | ((uint32_t)__half_as_ushort(hb) << 16);
}
__device__ __forceinline__ uint32_t hi2(uint2 v) { return (v.x >> 16) | (v.y & 0xffff0000u); }
__device__ __forceinline__ uint32_t lo2(uint2 v) { return (v.x & 0xffffu) | (v.y << 16); }

__device__ __forceinline__ void mma16816h(float (&c)[4], const uint32_t (&a)[4],
                                          uint32_t b0, uint32_t b1) {
    asm volatile(
        "mma.sync.aligned.m16n8k16.row.col.f32.f16.f16.f32 "
        "{%0,%1,%2,%3},{%4,%5,%6,%7},{%8,%9},{%0,%1,%2,%3};"
        : "+f"(c[0]), "+f"(c[1]), "+f"(c[2]), "+f"(c[3])
        : "r"(a[0]), "r"(a[1]), "r"(a[2]), "r"(a[3]), "r"(b0), "r"(b1));
}

// ============================================================================
// k_prep: weights -> fp16 fragments, BN fold
// ============================================================================
__global__ void __launch_bounds__(256) k_prep(
    const float* __restrict__ w1, const float* __restrict__ w2,
    const float* __restrict__ wf, const float* __restrict__ wfl,
    const float* __restrict__ gamma, const float* __restrict__ beta,
    const float* __restrict__ mean,  const float* __restrict__ var)
{
    int i = blockIdx.x * 256 + threadIdx.x;
    if (i < 64) {
        float s = gamma[i] * rsqrtf(var[i] + 1e-5f);
        g_bns[i] = s;
        g_bnb[i] = beta[i] - mean[i] * s;
    }
    if (i < 2 * 16 * 8 * 32 * 2) {           // 1x1 weights (16384)
        int j    = i & 1;
        int lane = (i >> 1) & 31;
        int nf   = (i >> 6) & 7;
        int ks   = (i >> 9) & 15;
        int wh   = i >> 13;
        int n   = nf * 8 + (lane >> 2);
        int ch0 = ks * 16 + (lane & 3) * 2 + j * 8;
        const float* w = wh ? w2 : w1;
        __half h0 = __float2half_rn(w[n * CIN + ch0]);
        __half h1 = __float2half_rn(w[n * CIN + ch0 + 1]);
        g_wd[(((wh * 16 + ks) * 8 + nf) * 32 + lane) * 2 + j] =
            (uint32_t)__half_as_ushort(h0) | ((uint32_t)__half_as_ushort(h1) << 16);
    }
    int m = i - 2 * 16 * 8 * 32 * 2;
    if (m >= 0 && m < 9 * 8 * 8 * 32 * 2) {  // 3x3 weights (36864)
        int j    = m & 1;
        int lane = (m >> 1) & 31;
        int nf   = (m >> 6) & 7;
        int ks   = (m >> 9) & 7;
        int tap  = m >> 12;
        int n   = nf * 8 + (lane >> 2);
        int ch0 = ks * 16 + (lane & 3) * 2 + j * 8;
        __half h0 = __float2half_rn(wf[n * (128 * 9) + ch0 * 9 + tap]);
        __half h1 = __float2half_rn(wf[n * (128 * 9) + (ch0 + 1) * 9 + tap]);
        g_wf[(((tap * 8 + ks) * 8 + nf) * 32 + lane) * 2 + j] =
            (uint32_t)__half_as_ushort(h0) | ((uint32_t)__half_as_ushort(h1) << 16);
    }
    int p = i - (2 * 16 * 8 * 32 * 2 + 9 * 8 * 8 * 32 * 2);
    if (p >= 0 && p < 9 * 4 * 32 * 2) {      // flow-conv weights (2304), hi+lo
        int j    = p & 1;
        int lane = (p >> 1) & 31;
        int ks   = (p >> 6) & 3;
        int tap  = p >> 8;
        int n   = lane >> 2;                  // only n<2 valid
        int ch0 = ks * 16 + (lane & 3) * 2 + j * 8;
        float v0 = (n < 2) ? wfl[n * 576 + ch0 * 9 + tap] : 0.f;
        float v1 = (n < 2) ? wfl[n * 576 + (ch0 + 1) * 9 + tap] : 0.f;
        uint32_t hi, lo; split2h(v0, v1, hi, lo);
        int base = ((tap * 4 + ks) * 32 + lane) * 4;
        g_wfl[base + j]     = hi;
        g_wfl[base + 2 + j] = lo;
    }
}

// profiler-steering no-op (keeps ncu sampling k2_mma)
__global__ void k_probe() {}

// ============================================================================
// k1: both 1x1 convs, fp16 single-pass mma, cp.async-staged A.
// Epilogue: fp16-hi-only packed g_y (half the write traffic).
// ============================================================================
__global__ void __launch_bounds__(256, 2) k1_mma(
    const float* __restrict__ x1, const float* __restrict__ x2)
{
    extern __shared__ float sX[];            // [2][32][260] floats
    const int tid = threadIdx.x, lane = tid & 31, wm = tid >> 5;
    const int pt = blockIdx.x, nb = blockIdx.y, wh = blockIdx.z;
    const int kq = lane & 3, nr = lane >> 2;
    const uint32_t sxa = smem_u32(sX);

    const float* X = (wh ? x2 : x1) + (size_t)nb * CIN * HW + pt * 256;
    const uint2* Bw = (const uint2*)g_wd + ((size_t)wh * 16 * 8 * 32 + lane);
    const int base = pt * 256 + wm * 32 + nr;

    float acc[2][8][4];
#pragma unroll
    for (int t = 0; t < 2; t++)
#pragma unroll
        for (int f = 0; f < 8; f++)
#pragma unroll
            for (int q = 0; q < 4; q++) acc[t][f][q] = 0.f;

    auto stage = [&](int r, int b) {
#pragma unroll
        for (int it = 0; it < 8; it++) {
            int i = tid + it * 256;
            int ch = i >> 6, quad = i & 63;   // ch 0..31
            const float* src = X + (size_t)(r * 32 + ch) * HW + quad * 4;
            uint32_t dst = sxa + (uint32_t)(b * XBUF + ch * 260 + quad * 4) * 4u;
            cp_async16(dst, src);
        }
    };

    stage(0, 0);
    cp_commit();

    for (int r = 0; r < 8; r++) {
        cp_wait0();
        __syncthreads();
        if (r < 7) { stage(r + 1, (r + 1) & 1); cp_commit(); }

        const float* buf = sX + (r & 1) * XBUF;
#pragma unroll
        for (int ss = 0; ss < 2; ss++) {
            const int ks = 2 * r + ss;
            const float* bc = buf + ss * 16 * 260;
            uint32_t Ahi[2][4];
#pragma unroll
            for (int t = 0; t < 2; t++) {
                const int p0 = wm * 32 + t * 16 + nr, p1 = p0 + 8;
                Ahi[t][0] = pack2hi(bc[(2 * kq) * 260 + p0],     bc[(2 * kq + 1) * 260 + p0]);
                Ahi[t][1] = pack2hi(bc[(2 * kq) * 260 + p1],     bc[(2 * kq + 1) * 260 + p1]);
                Ahi[t][2] = pack2hi(bc[(2 * kq + 8) * 260 + p0], bc[(2 * kq + 9) * 260 + p0]);
                Ahi[t][3] = pack2hi(bc[(2 * kq + 8) * 260 + p1], bc[(2 * kq + 9) * 260 + p1]);
            }
#pragma unroll
            for (int nf = 0; nf < 8; nf++) {
                uint2 b = Bw[(ks * 8 + nf) * 32];
                mma16816h(acc[0][nf], Ahi[0], b.x, b.y);
                mma16816h(acc[1][nf], Ahi[1], b.x, b.y);
            }
        }
    }

    // epilogue: fp16-hi pack to g_y [chunk][pix][4]
    uint32_t* gy = g_y + (size_t)nb * 16 * HW * 4;
#pragma unroll
    for (int t = 0; t < 2; t++) {
#pragma unroll
        for (int nf = 0; nf < 8; nf++) {
            const int chunk = wh * 8 + nf;
            const int pA = base + t * 16, pB = pA + 8;
            gy[((size_t)chunk * HW + pA) * 4 + kq] = pack2hi(acc[t][nf][0], acc[t][nf][1]);
            gy[((size_t)chunk * HW + pB) * 4 + kq] = pack2hi(acc[t][nf][2], acc[t][nf][3]);
        }
    }
}

// ============================================================================
// k2: conv3x3 (128->64) + BN + ReLU, fp16 single-pass mma.
// A staged from fp16-hi-only g_y (half traffic, LDS.32 fragments, no unpack).
// ============================================================================
__global__ void __launch_bounds__(256, 2) k2_mma()
{
    extern __shared__ uint32_t sA[];         // [2][3][2][260][4] u32
    const int tid = threadIdx.x, lane = tid & 31, wm = tid >> 5;
    const int y = blockIdx.x, nb = blockIdx.y;
    const int kq = lane & 3, nr = lane >> 2;
    const uint32_t saa = smem_u32(sA);

    float acc[2][8][4];
#pragma unroll
    for (int t = 0; t < 2; t++)
#pragma unroll
        for (int f = 0; f < 8; f++)
#pragma unroll
            for (int q = 0; q < 4; q++) acc[t][f][q] = 0.f;

    // zero the border columns (px slots 0 and 257) of both buffers, once
    for (int i = tid; i < 2 * 6 * 2 * 4; i += 256) {   // 96 words
        int j = i & 3, col = (i >> 2) & 1, rc = (i >> 3) % 6, b = i / 48;
        sA[b * ABUF + (rc * 260 + (col ? 257 : 0)) * 4 + j] = 0u;
    }

    const uint32_t* gyb = g_y + (size_t)nb * 16 * HW * 4;
    const uint2* BwL = (const uint2*)g_wf + lane;

    auto stage = [&](int ks, int b) {
#pragma unroll
        for (int it = 0; it < 6; it++) {
            int i = tid + it * 256;
            int px = i & 255;
            int rc = i >> 8;                 // 0..5: row*2+chunk
            int row = rc >> 1, chunk = rc & 1;
            int gyr = y + row - 1;
            int ok = ((unsigned)gyr < (unsigned)Hh) ? 16 : 0;
            int gyc = (gyr < 0) ? 0 : (gyr > Hh - 1 ? Hh - 1 : gyr);
            const uint32_t* src = gyb + ((size_t)(2 * ks + chunk) * HW + gyc * Ww + px) * 4;
            uint32_t dst = saa + (uint32_t)(b * ABUF + (rc * 260 + 1 + px) * 4) * 4u;
            cp_async16z(dst, src, ok);
        }
    };

    stage(0, 0);
    cp_commit();

    for (int ks = 0; ks < 8; ks++) {
        cp_wait0();
        __syncthreads();
        if (ks < 7) { stage(ks + 1, (ks + 1) & 1); cp_commit(); }

        const uint32_t* buf = sA + (ks & 1) * ABUF;
#pragma unroll
        for (int tap = 0; tap < 9; tap++) {
            const int row = tap / 3, dx = tap % 3 - 1;
            uint32_t Ahi[2][4];
#pragma unroll
            for (int t = 0; t < 2; t++) {
                const int p0 = wm * 32 + t * 16 + nr + dx + 1, p1 = p0 + 8;
                Ahi[t][0] = buf[((row * 2 + 0) * 260 + p0) * 4 + kq];
                Ahi[t][1] = buf[((row * 2 + 0) * 260 + p1) * 4 + kq];
                Ahi[t][2] = buf[((row * 2 + 1) * 260 + p0) * 4 + kq];
                Ahi[t][3] = buf[((row * 2 + 1) * 260 + p1) * 4 + kq];
            }
#pragma unroll
            for (int nf = 0; nf < 8; nf++) {
                uint2 b = BwL[((tap * 8 + ks) * 8 + nf) * 32];
                mma16816h(acc[0][nf], Ahi[0], b.x, b.y);
                mma16816h(acc[1][nf], Ahi[1], b.x, b.y);
            }
        }
    }

    // epilogue: BN + ReLU -> g_x2 packed fp16 hi|lo, [chunk8][pix][8]
    uint32_t* Xo = g_x2 + (size_t)nb * 8 * HW * 8;
#pragma unroll
    for (int t = 0; t < 2; t++) {
        const int op0 = y * Ww + wm * 32 + t * 16 + nr;
        const int op1 = op0 + 8;
#pragma unroll
        for (int nf = 0; nf < 8; nf++) {
            int ch = nf * 8 + 2 * kq;
            float s0 = g_bns[ch], b0 = g_bnb[ch];
            float s1 = g_bns[ch + 1], b1 = g_bnb[ch + 1];
            float r00 = acc[t][nf][0] * s0 + b0; r00 = r00 > 0.f ? r00 : 0.f;
            float r01 = acc[t][nf][1] * s1 + b1; r01 = r01 > 0.f ? r01 : 0.f;
            float r10 = acc[t][nf][2] * s0 + b0; r10 = r10 > 0.f ? r10 : 0.f;
            float r11 = acc[t][nf][3] * s1 + b1; r11 = r11 > 0.f ? r11 : 0.f;
            *(uint2*)&Xo[((size_t)nf * HW + op0) * 8 + 2 * kq] =
                make_uint2(split_pack_h(r00), split_pack_h(r01));
            *(uint2*)&Xo[((size_t)nf * HW + op1) * 8 + 2 * kq] =
                make_uint2(split_pack_h(r10), split_pack_h(r11));
        }
    }
}

// ============================================================================
// k3: conv3x3 (64 -> 2, pad 1) -> flow, via mma (3 passes, pass-outer order).
// ============================================================================
__global__ void __launch_bounds__(256) k3_mma()
{
    const int tid = threadIdx.x, lane = tid & 31, wm = tid >> 5;
    const int y = blockIdx.x, nb = blockIdx.y;
    const int kq = lane & 3, nr = lane >> 2;

    float acc[2][4];
#pragma unroll
    for (int t = 0; t < 2; t++)
#pragma unroll
        for (int q = 0; q < 4; q++) acc[t][q] = 0.f;

    const uint2* Au = (const uint2*)(g_x2 + (size_t)nb * 8 * HW * 8);
    const uint4* BwL = (const uint4*)g_wfl + lane;

#pragma unroll
    for (int tap = 0; tap < 9; tap++) {
        const int dy = tap / 3 - 1, dx = tap % 3 - 1;
        const int gyr = y + dy;
        const bool okY = (unsigned)gyr < (unsigned)Hh;
        int gp[4]; bool vg[4];
#pragma unroll
        for (int g = 0; g < 4; g++) {
            int gx = wm * 32 + g * 8 + nr + dx;
            vg[g] = okY && (unsigned)gx < (unsigned)Ww;
            gp[g] = gyr * Ww + gx;
        }

#pragma unroll
        for (int ks = 0; ks < 4; ks++) {
            const size_t cA = (size_t)(2 * ks) * HW, cB = cA + HW;
            uint2 q[4][2];
#pragma unroll
            for (int g = 0; g < 4; g++) {
                q[g][0] = vg[g] ? Au[(cA + gp[g]) * 4 + kq] : make_uint2(0u, 0u);
                q[g][1] = vg[g] ? Au[(cB + gp[g]) * 4 + kq] : make_uint2(0u, 0u);
            }
            uint4 b = BwL[(tap * 4 + ks) * 32];
            uint32_t Ahi[2][4], Alo[2][4];
#pragma unroll
            for (int t = 0; t < 2; t++) {
                Ahi[t][0] = hi2(q[2 * t][0]); Ahi[t][1] = hi2(q[2 * t + 1][0]);
                Ahi[t][2] = hi2(q[2 * t][1]); Ahi[t][3] = hi2(q[2 * t + 1][1]);
                Alo[t][0] = lo2(q[2 * t][0]); Alo[t][1] = lo2(q[2 * t + 1][0]);
                Alo[t][2] = lo2(q[2 * t][1]); Alo[t][3] = lo2(q[2 * t + 1][1]);
            }
#pragma unroll
            for (int pass = 0; pass < 3; pass++) {
#pragma unroll
                for (int t = 0; t < 2; t++) {
                    if (pass == 0)      mma16816h(acc[t], Ahi[t], b.x, b.y);
                    else if (pass == 1) mma16816h(acc[t], Alo[t], b.x, b.y);
                    else                mma16816h(acc[t], Ahi[t], b.z, b.w);
                }
            }
        }
    }

    if (kq == 0) {
        float* fx = g_flow + (size_t)(nb * 2) * HW;
        float* fy = fx + HW;
#pragma unroll
        for (int t = 0; t < 2; t++) {
            const int p0 = y * Ww + wm * 32 + t * 16 + nr;
            fx[p0]     = acc[t][0];
            fy[p0]     = acc[t][1];
            fx[p0 + 8] = acc[t][2];
            fy[p0 + 8] = acc[t][3];
        }
    }
}

// ============================================================================
// k4: flow_warp (torch repeat(c,1,1,1) batch-aliasing)
// ============================================================================
__global__ void __launch_bounds__(256) k_warp(
    const float* __restrict__ pred, float* __restrict__ out)
{
    const int idx = blockIdx.x * 256 + threadIdx.x;
    const int x = idx & (Ww - 1);
    const int y = (idx >> 8) & (Hh - 1);
    const int t = idx >> 15;
    const int fb = t & 3;

    const float fx = g_flow[(size_t)(fb * 2 + 0) * HW + y * Ww + x];
    const float fy = g_flow[(size_t)(fb * 2 + 1) * HW + y * Ww + x];

    const float gx = -1.f + 2.f * (float)x / (float)(Ww - 1);
    const float gy = -1.f + 2.f * (float)y / (float)(Hh - 1);
    const float sx = gx + fx / (float)Ww;
    const float sy = gy + fy / (float)Hh;
    const float ix = ((sx + 1.f) * (float)Ww - 1.f) * 0.5f;
    const float iy = ((sy + 1.f) * (float)Hh - 1.f) * 0.5f;

    const float x0f = floorf(ix), y0f = floorf(iy);
    const float wx = ix - x0f, wy = iy - y0f;
    const int x0 = (int)x0f, y0 = (int)y0f;

    const float* img = pred + (size_t)t * HW;
    auto samp = [&](int yy, int xx) -> float {
        return (xx >= 0 && xx < Ww && yy >= 0 && yy < Hh) ? img[yy * Ww + xx] : 0.f;
    };
    const float v00 = samp(y0, x0);
    const float v01 = samp(y0, x0 + 1);
    const float v10 = samp(y0 + 1, x0);
    const float v11 = samp(y0 + 1, x0 + 1);

    const float top = v00 * (1.f - wx) + v01 * wx;
    const float bot = v10 * (1.f - wx) + v11 * wx;
    out[idx] = top * (1.f - wy) + bot * wy;
}

// ============================================================================
// launch
// ============================================================================
extern "C" void kernel_launch(void* const* d_in, const int* in_sizes, int n_in,
                              void* d_out, int out_size)
{
    const float* t1_feature = (const float*)d_in[0];
    const float* t2_feature = (const float*)d_in[1];
    const float* t2_pred    = (const float*)d_in[2];
    const float* w_down1    = (const float*)d_in[3];
    const float* w_down2    = (const float*)d_in[4];
    const float* w_flow1    = (const float*)d_in[5];
    const float* bn_gamma   = (const float*)d_in[6];
    const float* bn_beta    = (const float*)d_in[7];
    const float* bn_mean    = (const float*)d_in[8];
    const float* bn_var     = (const float*)d_in[9];
    const float* w_flow2    = (const float*)d_in[10];
    float* out = (float*)d_out;

    cudaFuncSetAttribute(k1_mma, cudaFuncAttributeMaxDynamicSharedMemorySize, K1_SMEM);
    cudaFuncSetAttribute(k2_mma, cudaFuncAttributeMaxDynamicSharedMemorySize, K2_SMEM);

    k_prep<<<217, 256>>>(w_down1, w_down2, w_flow1, w_flow2,
                         bn_gamma, bn_beta, bn_mean, bn_var);
    k1_mma<<<dim3(128, NB, 2), 256, K1_SMEM>>>(t1_feature, t2_feature);
    k_probe<<<1, 32>>>();
    k2_mma<<<dim3(Hh, NB), 256, K2_SMEM>>>();
    k3_mma<<<dim3(Hh, NB), 256>>>();
    k_warp<<<(NB * CCLS * HW) / 256, 256>>>(t2_pred, out);
}